// round 14
// baseline (speedup 1.0000x reference)
#include <cuda_runtime.h>
#include <cuda_fp16.h>
#include <math.h>
#include <stdint.h>

#define B_DIM   4
#define L_DIM   2048
#define D_MODEL 1024
#define N_HEADS 16
#define D_HEAD  64
#define ML      (B_DIM * L_DIM)
#define N_PAIR  (B_DIM * N_HEADS)
#define N_CHUNK (L_DIM / 64)
#define DD      (D_MODEL * D_MODEL)
#define FS      65                       /* full fp32 smem stride */
#define HSX     33                       /* half-width fp32 smem stride */
#define HX      72                       /* fp16 tile stride (halves) */
#define F16T    (64 * HX)
#define F16H    (32 * HX)

/* ---------------- scratch (device globals; no runtime alloc) ---------------- */
__device__ float  g_kpre[ML * D_MODEL];
__device__ float  g_qpre[ML * D_MODEL];
__device__ float  g_vpre[ML * D_MODEL];
__device__ float  g_kn  [ML * D_MODEL];
__device__ float  g_qn  [ML * D_MODEL];
__device__ float  g_vs  [ML * D_MODEL];
__device__ float  g_bb  [ML * D_MODEL];
__device__ float  g_o   [ML * D_MODEL];
__device__ __half g_xh  [ML * D_MODEL];
__device__ __half g_oh  [ML * D_MODEL];
__device__ __half g_wsh [4 * DD];
__device__ __half g_wsl [4 * DD];

/* ---------------- fp32 -> fp16 splits, vectorized --------------------------- */
__device__ __forceinline__ void split4(float4 v, uint2& hi, uint2& lo) {
    __half2 h01 = __floats2half2_rn(v.x, v.y);
    __half2 h23 = __floats2half2_rn(v.z, v.w);
    __half2 l01 = __floats2half2_rn(v.x - __low2float(h01), v.y - __high2float(h01));
    __half2 l23 = __floats2half2_rn(v.z - __low2float(h23), v.w - __high2float(h23));
    hi = make_uint2(*(uint32_t*)&h01, *(uint32_t*)&h23);
    lo = make_uint2(*(uint32_t*)&l01, *(uint32_t*)&l23);
}

__global__ __launch_bounds__(256) void split_hi(
    const float4* __restrict__ src, uint2* __restrict__ hi, int n4)
{
    int i = blockIdx.x * blockDim.x + threadIdx.x;
    if (i >= n4) return;
    float4 v = src[i];
    __half2 h01 = __floats2half2_rn(v.x, v.y);
    __half2 h23 = __floats2half2_rn(v.z, v.w);
    hi[i] = make_uint2(*(uint32_t*)&h01, *(uint32_t*)&h23);
}

__global__ __launch_bounds__(256) void split_w4(
    const float4* __restrict__ w0, const float4* __restrict__ w1,
    const float4* __restrict__ w2, const float4* __restrict__ w3,
    uint2* __restrict__ hi, uint2* __restrict__ lo)
{
    int i = blockIdx.x * blockDim.x + threadIdx.x;
    int seg = i >> 18;
    int off = i & ((DD / 4) - 1);
    const float4* src = (seg == 0) ? w0 : (seg == 1) ? w1 : (seg == 2) ? w2 : w3;
    uint2 h, l;
    split4(src[off], h, l);
    hi[i] = h; lo[i] = l;
}

/* =================== tensor-core GEMM machinery (FP16) ====================== */
#define HS      40

__device__ __forceinline__ uint32_t smem_u32(const void* p) {
    uint32_t a;
    asm("{ .reg .u64 t; cvta.to.shared.u64 t, %1; cvt.u32.u64 %0, t; }"
        : "=r"(a) : "l"(p));
    return a;
}

#define LDSM_X4(r, a)                                                         \
    asm volatile("ldmatrix.sync.aligned.m8n8.x4.shared.b16 "                  \
                 "{%0,%1,%2,%3}, [%4];"                                       \
                 : "=r"((r)[0]), "=r"((r)[1]), "=r"((r)[2]), "=r"((r)[3])     \
                 : "r"(a))

#define MMA_F16B(d, a, b0, b1)                                                \
    asm volatile(                                                             \
        "mma.sync.aligned.m16n8k16.row.col.f32.f16.f16.f32 "                  \
        "{%0,%1,%2,%3}, {%4,%5,%6,%7}, {%8,%9}, {%0,%1,%2,%3};"               \
        : "+f"(d[0]), "+f"(d[1]), "+f"(d[2]), "+f"(d[3])                      \
        : "r"(a[0]), "r"(a[1]), "r"(a[2]), "r"(a[3]), "r"(b0), "r"(b1))

#define CP_ASYNC16(sa, gp)                                                    \
    asm volatile("cp.async.cg.shared.global [%0], [%1], 16;"                  \
                 :: "r"(sa), "l"(gp))

/* ---------- 2-pass mainloop (A hi; B hi+lo), 4-stage pipeline, 1 sync/tile -- */
#define QS_AH   0
#define QS_BH   10240
#define QS_BL   15360
#define QSTG    20480
#define QSM_BYTES (4 * QSTG)

#define GEMM2_BODY(Yptr, biasptr)                                             \
    extern __shared__ char smg[];                                             \
    const uint32_t sbase = smem_u32(smg);                                     \
    const int tid = threadIdx.x;                                              \
    const int bm = blockIdx.y * 128;                                          \
    const int lane = tid & 31, w = tid >> 5;                                  \
    const int wm = (w >> 1) * 32, wn = (w & 1) * 32;                          \
    const int g = lane >> 2, tg = lane & 3;                                   \
    const int arow = (lane & 7) + ((lane >> 3) & 1) * 8;                      \
    const int acol = (lane >> 4) * 8;                                         \
    const int brow = ((lane >> 4) & 1) * 8 + (lane & 7);                      \
    const int bcol = ((lane >> 3) & 1) * 8;                                   \
    const int r4 = tid >> 2, c4 = tid & 3;                                    \
    const uint32_t so = r4 * 80 + c4 * 16;                                    \
    float acc[2][4][4];                                                       \
    _Pragma("unroll")                                                         \
    for (int mt = 0; mt < 2; mt++)                                            \
        _Pragma("unroll")                                                     \
        for (int nt = 0; nt < 4; nt++)                                        \
            _Pragma("unroll")                                                 \
            for (int e = 0; e < 4; e++) acc[mt][nt][e] = 0.f;                 \
    const int n_tiles = K >> 5;                                               \
    QLOAD(0);                                                                 \
    QLOAD(1);                                                                 \
    QLOAD(2);                                                                 \
    for (int t = 0; t < n_tiles; t++) {                                       \
        const int rem = n_tiles - 1 - t;                                      \
        if (rem >= 2)      asm volatile("cp.async.wait_group 2;");            \
        else if (rem == 1) asm volatile("cp.async.wait_group 1;");            \
        else               asm volatile("cp.async.wait_group 0;");            \
        __syncthreads();                                                      \
        if (t + 3 < n_tiles) QLOAD(t + 3);                                    \
        const uint32_t sb = sbase + (t & 3) * QSTG;                           \
        _Pragma("unroll")                                                     \
        for (int kk = 0; kk < 2; kk++) {                                      \
            const int kc = kk * 16;                                           \
            uint32_t ah[2][4], bh[2][4], bl[2][4];                            \
            _Pragma("unroll")                                                 \
            for (int mt = 0; mt < 2; mt++) {                                  \
                uint32_t ad = sb + QS_AH +                                    \
                              ((wm + mt * 16 + arow) * HS + kc + acol) * 2;   \
                LDSM_X4(ah[mt], ad);                                          \
            }                                                                 \
            _Pragma("unroll")                                                 \
            for (int a2 = 0; a2 < 2; a2++) {                                  \
                uint32_t bd = sb + QS_BH +                                    \
                              ((wn + a2 * 16 + brow) * HS + kc + bcol) * 2;   \
                LDSM_X4(bh[a2], bd);                                          \
                LDSM_X4(bl[a2], bd + (QS_BL - QS_BH));                        \
            }                                                                 \
            _Pragma("unroll")                                                 \
            for (int mt = 0; mt < 2; mt++)                                    \
                _Pragma("unroll")                                             \
                for (int nt = 0; nt < 4; nt++) {                              \
                    const int hi2 = nt >> 1, p = (nt & 1) * 2;                \
                    MMA_F16B(acc[mt][nt], ah[mt], bh[hi2][p], bh[hi2][p+1]);  \
                    MMA_F16B(acc[mt][nt], ah[mt], bl[hi2][p], bl[hi2][p+1]);  \
                }                                                             \
        }                                                                     \
    }                                                                         \
    _Pragma("unroll")                                                         \
    for (int mt = 0; mt < 2; mt++) {                                          \
        const int row = bm + wm + mt * 16 + g;                                \
        _Pragma("unroll")                                                     \
        for (int nt = 0; nt < 4; nt++) {                                      \
            const int col = bnL + wn + nt * 8 + tg * 2;                       \
            const float b0 = (biasptr)[col], b1 = (biasptr)[col + 1];         \
            float2 v0 = make_float2(acc[mt][nt][0] + b0, acc[mt][nt][1] + b1);\
            float2 v1 = make_float2(acc[mt][nt][2] + b0, acc[mt][nt][3] + b1);\
            *(float2*)((Yptr) + (size_t)row * D_MODEL + col) = v0;            \
            *(float2*)((Yptr) + (size_t)(row + 8) * D_MODEL + col) = v1;      \
        }                                                                     \
    }

#define QLOAD(t) do {                                                         \
        const uint32_t _sb = sbase + ((t) & 3) * QSTG;                        \
        const int _kb = (t) << 5;                                             \
        const size_t _ga0 = (size_t)(bm + r4) * K + _kb + c4 * 8;             \
        const size_t _ga1 = (size_t)(bm + 64 + r4) * K + _kb + c4 * 8;        \
        const size_t _gb0 = (size_t)(bnG + r4) * K + _kb + c4 * 8;            \
        CP_ASYNC16(_sb + QS_AH + so,        Ahg + _ga0);                      \
        CP_ASYNC16(_sb + QS_AH + so + 5120, Ahg + _ga1);                      \
        CP_ASYNC16(_sb + QS_BH + so,        Bhg + _gb0);                      \
        CP_ASYNC16(_sb + QS_BL + so,        Blg + _gb0);                      \
        asm volatile("cp.async.commit_group;");                               \
    } while (0)

__global__ __launch_bounds__(256, 2) void gemm_qkv2(
    const __half* __restrict__ Ahg,
    const __half* __restrict__ Bhg, const __half* __restrict__ Blg,
    const float* __restrict__ bk, const float* __restrict__ bq,
    const float* __restrict__ bv,
    float* __restrict__ Yk, float* __restrict__ Yq, float* __restrict__ Yv,
    int M, int K)
{
    const int bnG = blockIdx.x * 64;
    const int seg = bnG >> 10;
    const int bnL = bnG & 1023;
    const float* bias = (seg == 0) ? bk : (seg == 1) ? bq : bv;
    float* Y = (seg == 0) ? Yk : (seg == 1) ? Yq : Yv;
    GEMM2_BODY(Y, bias)
}

__global__ __launch_bounds__(256, 2) void gemm_h2b(
    const __half* __restrict__ Ahg,
    const __half* __restrict__ Bhg, const __half* __restrict__ Blg,
    const float* __restrict__ bias, float* __restrict__ Y,
    int M, int K)
{
    const int bnG = blockIdx.x * 64;
    const int bnL = bnG;
    GEMM2_BODY(Y, bias)
}
#undef QLOAD

/* -------- prep8: 512 threads, 2 channels/thread, software prefetch ---------- */
__global__ __launch_bounds__(512, 2) void prep8(
    const float* __restrict__ x,
    const float* __restrict__ Wbeta, const float* __restrict__ bbeta,
    const float* __restrict__ ck, const float* __restrict__ cq,
    const float* __restrict__ cv)
{
    __shared__ float xs[8 * D_MODEL];
    __shared__ float eta_s[8][N_HEADS];

    const int bid = blockIdx.x;
    const int b = bid >> 8;
    const int l0 = (bid & 255) * 8;
    const int tid = threadIdx.x;
    const int d = tid * 2;
    const int h = tid >> 5;
    const int lane = tid & 31;
    const int w = tid >> 5;

#pragma unroll
    for (int i = 0; i < 4; i++) {
        int idx = i * 512 + tid;
        int t = idx >> 8, c = idx & 255;
        ((float4*)xs)[t * 256 + c] =
            *(const float4*)(x + ((size_t)(b * L_DIM + l0 + t)) * D_MODEL + c * 4);
    }
    __syncthreads();

    {
        const int t = w >> 1;
        const int hb0 = (w & 1) * 8;
        const float* xr = xs + t * D_MODEL;
#pragma unroll
        for (int hh = 0; hh < 8; hh++) {
            int hb = hb0 + hh;
            float s = 0.f;
            const float* wb = Wbeta + hb * D_MODEL;
            for (int k = lane * 4; k < D_MODEL; k += 128) {
                float4 xv = *(const float4*)(xr + k);
                float4 wv = *(const float4*)(wb + k);
                s += xv.x * wv.x + xv.y * wv.y + xv.z * wv.z + xv.w * wv.w;
            }
#pragma unroll
            for (int o = 16; o > 0; o >>= 1) s += __shfl_down_sync(0xffffffffu, s, o);
            if (lane == 0) eta_s[t][hb] = 1.f / (1.f + __expf(-(s + bbeta[hb])));
        }
    }

    float4 cwk[2], cwq[2], cwv[2];
#pragma unroll
    for (int c = 0; c < 2; c++) {
        cwk[c] = ((const float4*)ck)[d + c];
        cwq[c] = ((const float4*)cq)[d + c];
        cwv[c] = ((const float4*)cv)[d + c];
    }

    /* window slots 0..2: rows l0-3..l0-1 */
    float2 wk[4], wq[4], wv[4];
#pragma unroll
    for (int j = 0; j < 3; j++) {
        int ls = l0 - 3 + j;
        if (ls >= 0) {
            size_t base = ((size_t)(b * L_DIM + ls)) * D_MODEL + d;
            wk[j] = *(const float2*)&g_kpre[base];
            wq[j] = *(const float2*)&g_qpre[base];
            wv[j] = *(const float2*)&g_vpre[base];
        } else {
            wk[j] = wq[j] = wv[j] = make_float2(0.f, 0.f);
        }
    }
    /* prefetch row for t=0 */
    float2 nk, nq, nv;
    {
        size_t base = ((size_t)(b * L_DIM + l0)) * D_MODEL + d;
        nk = *(const float2*)&g_kpre[base];
        nq = *(const float2*)&g_qpre[base];
        nv = *(const float2*)&g_vpre[base];
    }
    __syncthreads();

#pragma unroll
    for (int t = 0; t < 8; t++) {
        wk[(t + 3) & 3] = nk;
        wq[(t + 3) & 3] = nq;
        wv[(t + 3) & 3] = nv;
        /* prefetch next token's rows before computing this one */
        if (t < 7) {
            size_t base = ((size_t)(b * L_DIM + l0 + t + 1)) * D_MODEL + d;
            nk = *(const float2*)&g_kpre[base];
            nq = *(const float2*)&g_qpre[base];
            nv = *(const float2*)&g_vpre[base];
        }
        float ak0 = 0.f, ak1 = 0.f, aq0 = 0.f, aq1 = 0.f, av0 = 0.f, av1 = 0.f;
#pragma unroll
        for (int j = 0; j < 4; j++) {
            const int sl = (t + j) & 3;
            float wk0 = ((const float*)&cwk[0])[j], wk1 = ((const float*)&cwk[1])[j];
            float wq0 = ((const float*)&cwq[0])[j], wq1 = ((const float*)&cwq[1])[j];
            float wv0 = ((const float*)&cwv[0])[j], wv1 = ((const float*)&cwv[1])[j];
            ak0 += wk[sl].x * wk0; ak1 += wk[sl].y * wk1;
            aq0 += wq[sl].x * wq0; aq1 += wq[sl].y * wq1;
            av0 += wv[sl].x * wv0; av1 += wv[sl].y * wv1;
        }
        float sk = ak0 * ak0 + ak1 * ak1;
        float sq = aq0 * aq0 + aq1 * aq1;
#pragma unroll
        for (int o = 16; o > 0; o >>= 1) {
            sk += __shfl_xor_sync(0xffffffffu, sk, o);
            sq += __shfl_xor_sync(0xffffffffu, sq, o);
        }
        const float rkn = 1.f / (sqrtf(sk) + 1e-6f);
        const float rqn = 1.f / (sqrtf(sq) + 1e-6f);
        const float e = eta_s[t][h];

        float kn0 = ak0 * rkn, kn1 = ak1 * rkn;
        float qn0 = aq0 * rqn, qn1 = aq1 * rqn;
        float sv0 = av0 / (1.f + __expf(-av0));
        float sv1 = av1 / (1.f + __expf(-av1));
        size_t obase = (((size_t)(b * N_HEADS + h)) * L_DIM + l0 + t) * D_HEAD + (d & 63);
        *(float2*)&g_kn[obase] = make_float2(kn0, kn1);
        *(float2*)&g_qn[obase] = make_float2(qn0, qn1);
        *(float2*)&g_vs[obase] = make_float2(e * sv0, e * sv1);
        *(float2*)&g_bb[obase] = make_float2(e * kn0, e * kn1);
    }
}

/* ---------------- chunked o2b weighted delta-rule scan (round-13 version) --- */
#define SPLIT_ST(ah_, al_, idx_, val_) do {                                   \
        __half _hh = __float2half_rn(val_);                                   \
        (ah_)[idx_] = _hh;                                                    \
        (al_)[idx_] = __float2half_rn((val_) - __half2float(_hh));            \
    } while (0)

#define DSM_BYTES ((2 * 64 * FS + 3 * 64 * HSX + 512 + 256) * 4 +             \
                   (10 * F16T + 8 * F16H) * 2)

__global__ __launch_bounds__(256) void delta_kernel()
{
    extern __shared__ float smd[];
    float* Ts   = smd;
    float* Qk   = Ts + 64 * FS;
    float* Wt   = Qk + 64 * FS;
    float* Wa   = Wt + 64 * HSX;
    float* Us   = Wa + 64 * HSX;
    float* invD = Us + 64 * HSX;
    float* Mb   = invD + 512;
    __half* Kh   = (__half*)(Mb + 256);
    __half* Kl   = Kh  + F16T;
    __half* Qh   = Kl  + F16T;
    __half* Ql   = Qh  + F16T;
    __half* Bh2  = Ql  + F16T;
    __half* Bl2  = Bh2 + F16T;
    __half* KTh  = Bl2 + F16T;
    __half* KTl  = KTh + F16T;
    __half* Sh   = KTl + F16T;
    __half* Sl   = Sh  + F16T;
    __half* WtTh = Sl  + F16T;
    __half* WtTl = WtTh + F16H;
    __half* WaTh = WtTl + F16H;
    __half* WaTl = WaTh + F16H;
    __half* UTh  = WaTl + F16H;
    __half* UTl  = UTh + F16H;
    __half* UwTh = UTl + F16H;
    __half* UwTl = UwTh + F16H;

    const int tid = threadIdx.x;
    const int lane = tid & 31, w = tid >> 5;
    const int g = lane >> 2, tg = lane & 3;
    const int arow = (lane & 7) + ((lane >> 3) & 1) * 8;
    const int acol = (lane >> 4) * 8;
    const int brow = ((lane >> 4) & 1) * 8 + (lane & 7);
    const int bcol = ((lane >> 3) & 1) * 8;

    const int pair = blockIdx.x >> 1;
    const int half = blockIdx.x & 1;
    const int col0 = half * 32;
    const int b = pair >> 4, h = pair & 15;

    for (int i = tid; i < 64 * HSX; i += 256) { Wt[i] = 0.f; Wa[i] = 0.f; }

    const size_t pbase = (size_t)pair * L_DIM * D_HEAD;
    const uint32_t khB = smem_u32(Kh), klB = smem_u32(Kl);

    for (int chunk = 0; chunk < N_CHUNK; chunk++) {
        __syncthreads();
        const size_t cb = pbase + (size_t)chunk * 64 * D_HEAD;
        for (int i2 = tid; i2 < 4096; i2 += 256) {
            int r = i2 >> 6, c = i2 & 63;
            float kv = g_kn[cb + i2];
            float qv = g_qn[cb + i2];
            float bv = g_bb[cb + i2];
            SPLIT_ST(Kh, Kl, r * HX + c, kv);
            SPLIT_ST(KTh, KTl, c * HX + r, kv);
            SPLIT_ST(Qh, Ql, r * HX + c, qv);
            SPLIT_ST(Bh2, Bl2, r * HX + c, bv);
        }
        for (int i2 = tid; i2 < 2048; i2 += 256) {
            int r = i2 >> 5, c = i2 & 31;
            Us[r * HSX + c] = g_vs[cb + r * 64 + col0 + c];
        }
        for (int i2 = tid; i2 < 2048; i2 += 256) {
            int m = i2 >> 5, n = i2 & 31;
            SPLIT_ST(WtTh, WtTl, n * HX + m, Wt[m * HSX + n]);
            SPLIT_ST(WaTh, WaTl, n * HX + m, Wa[m * HSX + n]);
        }
        __syncthreads();

        const float ts    = (float)(chunk * 64);
        const float tri0  = 0.5f * (1.f + ts) * ts;
        const float denw  = 0.5f * (65.f + ts) * (64.f + ts);
        const float Ssum  = 64.f * ts + 2080.f;
        const float coef1 = (ts / (ts + 64.f)) * ((1.f + ts) / (ts + 65.f));
        const float coef2 = (64.f / (ts + 64.f)) * ((2.f * ts + 65.f) / (ts + 65.f));

        /* PASS 1a: [B;Q] @ K^T -> T (warps 0-3, tril) / QK (warps 4-7) */
        {
            const uint32_t ahB = smem_u32((w < 4) ? Bh2 : Qh);
            const uint32_t alB = smem_u32((w < 4) ? Bl2 : Ql);
            const int r0 = (w & 3) * 16;
            float acc[8][4];
#pragma unroll
            for (int j = 0; j < 8; j++)
#pragma unroll
                for (int e = 0; e < 4; e++) acc[j][e] = 0.f;

#pragma unroll
            for (int ks = 0; ks < 4; ks++) {
                const int kc = ks * 16;
                uint32_t ah[4], al[4], bh[4][4], bl[4][4];
                const uint32_t aoff = ((r0 + arow) * HX + kc + acol) * 2;
                LDSM_X4(ah, ahB + aoff);
                LDSM_X4(al, alB + aoff);
#pragma unroll
                for (int nt = 0; nt < 4; nt++) {
                    const uint32_t boff = ((nt * 16 + brow) * HX + kc + bcol) * 2;
                    LDSM_X4(bh[nt], khB + boff);
                    LDSM_X4(bl[nt], klB + boff);
                }
#pragma unroll
                for (int j = 0; j < 8; j++) {
                    const int grp = j >> 1, p = (j & 1) * 2;
                    MMA_F16B(acc[j], ah, bh[grp][p], bh[grp][p + 1]);
                    MMA_F16B(acc[j], ah, bl[grp][p], bl[grp][p + 1]);
                    MMA_F16B(acc[j], al, bh[grp][p], bh[grp][p + 1]);
                }
            }
            if (w < 4) {
#pragma unroll
                for (int j = 0; j < 8; j++) {
                    const int C = j * 8 + tg * 2;
                    const int R1 = r0 + g, R2 = r0 + g + 8;
                    Ts[R1 * FS + C]     = (R1 > C)     ? acc[j][0] : 0.f;
                    Ts[R1 * FS + C + 1] = (R1 > C + 1) ? acc[j][1] : 0.f;
                    Ts[R2 * FS + C]     = (R2 > C)     ? acc[j][2] : 0.f;
                    Ts[R2 * FS + C + 1] = (R2 > C + 1) ? acc[j][3] : 0.f;
                }
            } else {
#pragma unroll
                for (int j = 0; j < 8; j++) {
                    const int C = j * 8 + tg * 2;
                    const int R1 = r0 + g, R2 = r0 + g + 8;
                    Qk[R1 * FS + C]     = acc[j][0];
                    Qk[R1 * FS + C + 1] = acc[j][1];
                    Qk[R2 * FS + C]     = acc[j][2];
                    Qk[R2 * FS + C + 1] = acc[j][3];
                }
            }
        }

        /* PASS 1b: RHS = V - B @ Wt */
        {
            const uint32_t b2h = smem_u32(Bh2), b2l = smem_u32(Bl2);
            const uint32_t wth = smem_u32(WtTh), wtl = smem_u32(WtTl);
            const int bm0 = (w & 3) * 16;
            const int bn0 = (w >> 2) * 16;
            float accB[2][4];
#pragma unroll
            for (int nt = 0; nt < 2; nt++)
#pragma unroll
                for (int e = 0; e < 4; e++) accB[nt][e] = 0.f;
#pragma unroll
            for (int ks = 0; ks < 4; ks++) {
                const int kc = ks * 16;
                uint32_t ah[4], al[4], bh[4], bl[4];
                const uint32_t aoff = ((bm0 + arow) * HX + kc + acol) * 2;
                LDSM_X4(ah, b2h + aoff);
                LDSM_X4(al, b2l + aoff);
                const uint32_t boff = ((bn0 + brow) * HX + kc + bcol) * 2;
                LDSM_X4(bh, wth + boff);
                LDSM_X4(bl, wtl + boff);
#pragma unroll
                for (int nt = 0; nt < 2; nt++) {
                    const int p = nt * 2;
                    MMA_F16B(accB[nt], ah, bh[p], bh[p + 1]);
                    MMA_F16B(accB[nt], ah, bl[p], bl[p + 1]);
                    MMA_F16B(accB[nt], al, bh[p], bh[p + 1]);
                }
            }
#pragma unroll
            for (int nt = 0; nt < 2; nt++) {
                const int col = bn0 + nt * 8 + tg * 2;
                const int R1 = bm0 + g, R2 = bm0 + g + 8;
                Us[R1 * HSX + col]     -= accB[nt][0];
                Us[R1 * HSX + col + 1] -= accB[nt][1];
                Us[R2 * HSX + col]     -= accB[nt][2];
                Us[R2 * HSX + col + 1] -= accB[nt][3];
            }
        }
        __syncthreads();

        /* C0: invert the 8 unit-lower 8x8 diagonal blocks */
        if (tid < 64) {
            const int blk = tid >> 3, c = tid & 7;
            const int r0 = blk * 8;
            float xcol[8];
#pragma unroll
            for (int r = 0; r < 8; r++) {
                float s = (r == c) ? 1.f : 0.f;
                for (int k2 = c; k2 < r; k2++)
                    s -= Ts[(r0 + r) * FS + r0 + k2] * xcol[k2];
                xcol[r] = s;
            }
#pragma unroll
            for (int r = 0; r < 8; r++) invD[(r0 + r) * 8 + c] = xcol[r];
        }
        __syncthreads();

        /* C: blocked forward substitution (I+T) U = RHS */
        {
            const int cc = tid & 31, rr = tid >> 5;
            for (int ib = 0; ib < 8; ib++) {
                const int r0 = ib * 8;
                float s = 0.f;
                for (int j = 0; j < r0; j++)
                    s += Ts[(r0 + rr) * FS + j] * Us[j * HSX + cc];
                float rhs = Us[(r0 + rr) * HSX + cc] - s;
                Mb[rr * 32 + cc] = rhs;
                __syncthreads();
                s = rhs;
                for (int k2 = 0; k2 < rr; k2++)
                    s += invD[(r0 + rr) * 8 + k2] * Mb[k2 * 32 + cc];
                Us[(r0 + rr) * HSX + cc] = s;
                __syncthreads();
            }
        }

        /* conversions: S = weights o QK; U^T and (U*w)^T in fp16 hi/lo */
        for (int i2 = tid; i2 < 4096; i2 += 256) {
            int r = i2 >> 6, c = i2 & 63;
            float rr2 = (float)r;
            float cs_r = (rr2 + 1.f) * ts + 0.5f * (rr2 + 1.f) * (rr2 + 2.f);
            float rdiv = 1.f / (tri0 + cs_r);
            float kf = (float)c;
            float csk_m = kf * ts + 0.5f * kf * (kf + 1.f);
            float num = cs_r - csk_m;
            float sfac = (num >= 0.f) ? num * rdiv : 0.f;
            float sv = sfac * Qk[r * FS + c];
            SPLIT_ST(Sh, Sl, r * HX + c, sv);
        }
        for (int i2 = tid; i2 < 2048; i2 += 256) {
            int c = i2 >> 6, r = i2 & 63;
            float u = Us[r * HSX + c];
            float rr2 = (float)r;
            float idxr = ts + rr2 + 1.f;
            float csrr = (rr2 + 1.f) * ts + 0.5f * (rr2 + 1.f) * (rr2 + 2.f);
            float wr = (idxr + Ssum - csrr) / denw;
            SPLIT_ST(UTh, UTl, c * HX + r, u);
            SPLIT_ST(UwTh, UwTl, c * HX + r, u * wr);
        }
        __syncthreads();

        /* PASS 2: warps 0-3 -> O (D + F); warps 4-7 -> H (W updates) */
        if (w < 4) {
            const int r0 = w * 16;
            const uint32_t qhB = smem_u32(Qh), qlB = smem_u32(Ql);
            const uint32_t shB = smem_u32(Sh), slB = smem_u32(Sl);
            const uint32_t wah = smem_u32(WaTh), wal = smem_u32(WaTl);
            const uint32_t wth = smem_u32(WtTh), wtl = smem_u32(WtTl);
            const uint32_t uth = smem_u32(UTh), utl = smem_u32(UTl);
            float aA[4][4], aT[4][4], aF[4][4];
#pragma unroll
            for (int nt = 0; nt < 4; nt++)
#pragma unroll
                for (int e = 0; e < 4; e++) { aA[nt][e] = 0.f; aT[nt][e] = 0.f; aF[nt][e] = 0.f; }

#pragma unroll
            for (int ks = 0; ks < 4; ks++) {
                const int kc = ks * 16;
                const uint32_t aoff = ((r0 + arow) * HX + kc + acol) * 2;
                uint32_t qh[4], ql[4], sh[4], sl[4];
                LDSM_X4(qh, qhB + aoff);
                LDSM_X4(ql, qlB + aoff);
                LDSM_X4(sh, shB + aoff);
                LDSM_X4(sl, slB + aoff);
                uint32_t bwa[2][4], bwa2[2][4], bwt[2][4], bwt2[2][4], bu[2][4], bu2[2][4];
#pragma unroll
                for (int a2 = 0; a2 < 2; a2++) {
                    const uint32_t boff = ((a2 * 16 + brow) * HX + kc + bcol) * 2;
                    LDSM_X4(bwa[a2], wah + boff);
                    LDSM_X4(bwa2[a2], wal + boff);
                    LDSM_X4(bwt[a2], wth + boff);
                    LDSM_X4(bwt2[a2], wtl + boff);
                    LDSM_X4(bu[a2], uth + boff);
                    LDSM_X4(bu2[a2], utl + boff);
                }
#pragma unroll
                for (int nt = 0; nt < 4; nt++) {
                    const int grp = nt >> 1, p = (nt & 1) * 2;
                    MMA_F16B(aA[nt], qh, bwa[grp][p], bwa[grp][p + 1]);
                    MMA_F16B(aA[nt], qh, bwa2[grp][p], bwa2[grp][p + 1]);
                    MMA_F16B(aA[nt], ql, bwa[grp][p], bwa[grp][p + 1]);
                    MMA_F16B(aT[nt], qh, bwt[grp][p], bwt[grp][p + 1]);
                    MMA_F16B(aT[nt], qh, bwt2[grp][p], bwt2[grp][p + 1]);
                    MMA_F16B(aT[nt], ql, bwt[grp][p], bwt[grp][p + 1]);
                    MMA_F16B(aF[nt], sh, bu[grp][p], bu[grp][p + 1]);
                    MMA_F16B(aF[nt], sh, bu2[grp][p], bu2[grp][p + 1]);
                    MMA_F16B(aF[nt], sl, bu[grp][p], bu[grp][p + 1]);
                }
            }
            const int r1 = r0 + g, r2 = r1 + 8;
            float f1 = (float)r1, f2 = (float)r2;
            float cs1 = (f1 + 1.f) * ts + 0.5f * (f1 + 1.f) * (f1 + 2.f);
            float cs2 = (f2 + 1.f) * ts + 0.5f * (f2 + 1.f) * (f2 + 2.f);
            float ar1 = tri0 / (tri0 + cs1);
            float ar2 = tri0 / (tri0 + cs2);
#pragma unroll
            for (int nt = 0; nt < 4; nt++) {
                const int cg = h * 64 + col0 + nt * 8 + tg * 2;
                int l1 = chunk * 64 + r1, l2 = chunk * 64 + r2;
                float2 v1 = make_float2(
                    ar1 * aA[nt][0] + (1.f - ar1) * aT[nt][0] + aF[nt][0],
                    ar1 * aA[nt][1] + (1.f - ar1) * aT[nt][1] + aF[nt][1]);
                float2 v2 = make_float2(
                    ar2 * aA[nt][2] + (1.f - ar2) * aT[nt][2] + aF[nt][2],
                    ar2 * aA[nt][3] + (1.f - ar2) * aT[nt][3] + aF[nt][3]);
                *(float2*)&g_o[((size_t)(b * L_DIM + l1)) * D_MODEL + cg] = v1;
                *(float2*)&g_o[((size_t)(b * L_DIM + l2)) * D_MODEL + cg] = v2;
            }
        } else {
            const int m0 = (w - 4) * 16;
            const uint32_t kth = smem_u32(KTh), ktl = smem_u32(KTl);
            const uint32_t uth = smem_u32(UTh), utl = smem_u32(UTl);
            const uint32_t uwh = smem_u32(UwTh), uwl = smem_u32(UwTl);
            float p1a[4][4], p2a[4][4];
#pragma unroll
            for (int nt = 0; nt < 4; nt++)
#pragma unroll
                for (int e = 0; e < 4; e++) { p1a[nt][e] = 0.f; p2a[nt][e] = 0.f; }

#pragma unroll
            for (int ks = 0; ks < 4; ks++) {
                const int kc = ks * 16;
                const uint32_t aoff = ((m0 + arow) * HX + kc + acol) * 2;
                uint32_t kh2[4], kl2[4];
                LDSM_X4(kh2, kth + aoff);
                LDSM_X4(kl2, ktl + aoff);
                uint32_t bu[2][4], bu2[2][4], bw[2][4], bw2[2][4];
#pragma unroll
                for (int a2 = 0; a2 < 2; a2++) {
                    const uint32_t boff = ((a2 * 16 + brow) * HX + kc + bcol) * 2;
                    LDSM_X4(bu[a2], uth + boff);
                    LDSM_X4(bu2[a2], utl + boff);
                    LDSM_X4(bw[a2], uwh + boff);
                    LDSM_X4(bw2[a2], uwl + boff);
                }
#pragma unroll
                for (int nt = 0; nt < 4; nt++) {
                    const int grp = nt >> 1, p = (nt & 1) * 2;
                    MMA_F16B(p1a[nt], kh2, bu[grp][p], bu[grp][p + 1]);
                    MMA_F16B(p1a[nt], kh2, bu2[grp][p], bu2[grp][p + 1]);
                    MMA_F16B(p1a[nt], kl2, bu[grp][p], bu[grp][p + 1]);
                    MMA_F16B(p2a[nt], kh2, bw[grp][p], bw[grp][p + 1]);
                    MMA_F16B(p2a[nt], kh2, bw2[grp][p], bw2[grp][p + 1]);
                    MMA_F16B(p2a[nt], kl2, bw[grp][p], bw[grp][p + 1]);
                }
            }
            const int m1 = m0 + g, m2 = m1 + 8;
#pragma unroll
            for (int nt = 0; nt < 4; nt++) {
                const int n = nt * 8 + tg * 2;
#pragma unroll
                for (int cc2 = 0; cc2 < 2; cc2++) {
                    int i1 = m1 * HSX + n + cc2;
                    float wo = Wt[i1];
                    Wa[i1] = coef1 * Wa[i1] + coef2 * wo + p2a[nt][cc2];
                    Wt[i1] = wo + p1a[nt][cc2];
                    int i2x = m2 * HSX + n + cc2;
                    wo = Wt[i2x];
                    Wa[i2x] = coef1 * Wa[i2x] + coef2 * wo + p2a[nt][2 + cc2];
                    Wt[i2x] = wo + p1a[nt][2 + cc2];
                }
            }
        }
    }
}

/* -------- RMS norm over head dim + fp16 (hi only) for final 2-pass GEMM ----- */
__global__ __launch_bounds__(256) void rms_split(const float* __restrict__ rms_w)
{
    const int bl = blockIdx.x, tid = threadIdx.x;
    float4 v = ((const float4*)g_o)[(size_t)bl * 256 + tid];
    float ss = v.x * v.x + v.y * v.y + v.z * v.z + v.w * v.w;
#pragma unroll
    for (int o = 8; o > 0; o >>= 1) ss += __shfl_xor_sync(0xffffffffu, ss, o);
    float scale = rsqrtf(ss * (1.f / 64.f) + 1e-6f);
    float4 rw = ((const float4*)rms_w)[tid & 15];
    float a0 = v.x * scale * rw.x, a1 = v.y * scale * rw.y;
    float a2 = v.z * scale * rw.z, a3 = v.w * scale * rw.w;
    __half2 h01 = __floats2half2_rn(a0, a1);
    __half2 h23 = __floats2half2_rn(a2, a3);
    ((uint2*)g_oh)[(size_t)bl * 256 + tid] = make_uint2(*(uint32_t*)&h01, *(uint32_t*)&h23);
}

/* ------------------------------- launcher ----------------------------------*/
extern "C" void kernel_launch(void* const* d_in, const int* in_sizes, int n_in,
                              void* d_out, int out_size)
{
    (void)in_sizes; (void)n_in; (void)out_size;
    const float* x     = (const float*)d_in[0];
    const float* Wk    = (const float*)d_in[1];
    const float* bk    = (const float*)d_in[2];
    const float* Wq    = (const float*)d_in[3];
    const float* bq    = (const float*)d_in[4];
    const float* Wv    = (const float*)d_in[5];
    const float* bv    = (const float*)d_in[6];
    const float* Wbeta = (const float*)d_in[7];
    const float* bbeta = (const float*)d_in[8];
    const float* ck    = (const float*)d_in[9];
    const float* cq    = (const float*)d_in[10];
    const float* cv    = (const float*)d_in[11];
    const float* rms_w = (const float*)d_in[12];
    const float* Wout  = (const float*)d_in[13];
    const float* bout  = (const float*)d_in[14];
    float* out = (float*)d_out;

    float *kpre, *qpre, *vpre;
    __half *xh, *oh, *wsh, *wsl;
    cudaGetSymbolAddress((void**)&kpre, g_kpre);
    cudaGetSymbolAddress((void**)&qpre, g_qpre);
    cudaGetSymbolAddress((void**)&vpre, g_vpre);
    cudaGetSymbolAddress((void**)&xh, g_xh);
    cudaGetSymbolAddress((void**)&oh, g_oh);
    cudaGetSymbolAddress((void**)&wsh, g_wsh);
    cudaGetSymbolAddress((void**)&wsl, g_wsl);

    split_hi<<<(ML * D_MODEL / 4 + 255) / 256, 256>>>(
        (const float4*)x, (uint2*)xh, ML * D_MODEL / 4);
    split_w4<<<(4 * DD / 4) / 256, 256>>>(
        (const float4*)Wk, (const float4*)Wq, (const float4*)Wv,
        (const float4*)Wout, (uint2*)wsh, (uint2*)wsl);

    cudaFuncSetAttribute(gemm_qkv2, cudaFuncAttributeMaxDynamicSharedMemorySize,
                         QSM_BYTES);
    cudaFuncSetAttribute(gemm_h2b, cudaFuncAttributeMaxDynamicSharedMemorySize,
                         QSM_BYTES);

    gemm_qkv2<<<dim3(48, 64), 256, QSM_BYTES>>>(
        xh, wsh, wsl, bk, bq, bv, kpre, qpre, vpre, ML, D_MODEL);

    prep8<<<B_DIM * (L_DIM / 8), 512>>>(x, Wbeta, bbeta, ck, cq, cv);

    cudaFuncSetAttribute(delta_kernel, cudaFuncAttributeMaxDynamicSharedMemorySize,
                         DSM_BYTES);
    delta_kernel<<<2 * N_PAIR, 256, DSM_BYTES>>>();

    rms_split<<<ML, 256>>>(rms_w);

    gemm_h2b<<<dim3(16, 64), 256, QSM_BYTES>>>(
        oh, wsh + 3 * DD, wsl + 3 * DD, bout, out, ML, D_MODEL);
}

// round 15
// speedup vs baseline: 1.0141x; 1.0141x over previous
#include <cuda_runtime.h>
#include <cuda_fp16.h>
#include <math.h>
#include <stdint.h>

#define B_DIM   4
#define L_DIM   2048
#define D_MODEL 1024
#define N_HEADS 16
#define D_HEAD  64
#define ML      (B_DIM * L_DIM)
#define N_PAIR  (B_DIM * N_HEADS)
#define N_CHUNK (L_DIM / 64)
#define DD      (D_MODEL * D_MODEL)
#define FS      65                       /* full fp32 smem stride */
#define HSX     33                       /* half-width fp32 smem stride */
#define HX      72                       /* fp16 tile stride (halves) */
#define F16T    (64 * HX)
#define F16H    (32 * HX)

/* ---------------- scratch (device globals; no runtime alloc) ---------------- */
__device__ float  g_kpre[ML * D_MODEL];
__device__ float  g_qpre[ML * D_MODEL];
__device__ float  g_vpre[ML * D_MODEL];
__device__ float  g_kn  [ML * D_MODEL];
__device__ float  g_qn  [ML * D_MODEL];
__device__ float  g_vs  [ML * D_MODEL];
__device__ float  g_bb  [ML * D_MODEL];
__device__ float  g_o   [ML * D_MODEL];
__device__ __half g_xh  [ML * D_MODEL];
__device__ __half g_oh  [ML * D_MODEL];
__device__ __half g_wsh [4 * DD];
__device__ __half g_wsl [4 * DD];

/* ---------------- fp32 -> fp16 splits, vectorized --------------------------- */
__device__ __forceinline__ void split4(float4 v, uint2& hi, uint2& lo) {
    __half2 h01 = __floats2half2_rn(v.x, v.y);
    __half2 h23 = __floats2half2_rn(v.z, v.w);
    __half2 l01 = __floats2half2_rn(v.x - __low2float(h01), v.y - __high2float(h01));
    __half2 l23 = __floats2half2_rn(v.z - __low2float(h23), v.w - __high2float(h23));
    hi = make_uint2(*(uint32_t*)&h01, *(uint32_t*)&h23);
    lo = make_uint2(*(uint32_t*)&l01, *(uint32_t*)&l23);
}

__global__ __launch_bounds__(256) void split_hi(
    const float4* __restrict__ src, uint2* __restrict__ hi, int n4)
{
    int i = blockIdx.x * blockDim.x + threadIdx.x;
    if (i >= n4) return;
    float4 v = src[i];
    __half2 h01 = __floats2half2_rn(v.x, v.y);
    __half2 h23 = __floats2half2_rn(v.z, v.w);
    hi[i] = make_uint2(*(uint32_t*)&h01, *(uint32_t*)&h23);
}

__global__ __launch_bounds__(256) void split_w4(
    const float4* __restrict__ w0, const float4* __restrict__ w1,
    const float4* __restrict__ w2, const float4* __restrict__ w3,
    uint2* __restrict__ hi, uint2* __restrict__ lo)
{
    int i = blockIdx.x * blockDim.x + threadIdx.x;
    int seg = i >> 18;
    int off = i & ((DD / 4) - 1);
    const float4* src = (seg == 0) ? w0 : (seg == 1) ? w1 : (seg == 2) ? w2 : w3;
    uint2 h, l;
    split4(src[off], h, l);
    hi[i] = h; lo[i] = l;
}

/* =================== tensor-core GEMM machinery (FP16) ====================== */
#define HS      40

__device__ __forceinline__ uint32_t smem_u32(const void* p) {
    uint32_t a;
    asm("{ .reg .u64 t; cvta.to.shared.u64 t, %1; cvt.u32.u64 %0, t; }"
        : "=r"(a) : "l"(p));
    return a;
}

#define LDSM_X4(r, a)                                                         \
    asm volatile("ldmatrix.sync.aligned.m8n8.x4.shared.b16 "                  \
                 "{%0,%1,%2,%3}, [%4];"                                       \
                 : "=r"((r)[0]), "=r"((r)[1]), "=r"((r)[2]), "=r"((r)[3])     \
                 : "r"(a))

#define MMA_F16B(d, a, b0, b1)                                                \
    asm volatile(                                                             \
        "mma.sync.aligned.m16n8k16.row.col.f32.f16.f16.f32 "                  \
        "{%0,%1,%2,%3}, {%4,%5,%6,%7}, {%8,%9}, {%0,%1,%2,%3};"               \
        : "+f"(d[0]), "+f"(d[1]), "+f"(d[2]), "+f"(d[3])                      \
        : "r"(a[0]), "r"(a[1]), "r"(a[2]), "r"(a[3]), "r"(b0), "r"(b1))

#define CP_ASYNC16(sa, gp)                                                    \
    asm volatile("cp.async.cg.shared.global [%0], [%1], 16;"                  \
                 :: "r"(sa), "l"(gp))

/* ---------- 2-pass mainloop, CTA tile 128x128, 3-stage pipeline ------------
   8 warps of 64x32; A hi only; B hi+lo.  A traffic halves vs 128x64.        */
#define QS_AH   0
#define QS_BH   10240
#define QS_BL   20480
#define QSTG    30720
#define QSM_BYTES (3 * QSTG)

#define GEMM2_BODY(Yptr, biasptr)                                             \
    extern __shared__ char smg[];                                             \
    const uint32_t sbase = smem_u32(smg);                                     \
    const int tid = threadIdx.x;                                              \
    const int bm = blockIdx.y * 128;                                          \
    const int lane = tid & 31, w = tid >> 5;                                  \
    const int wm = (w >> 2) * 64, wn = (w & 3) * 32;                          \
    const int g = lane >> 2, tg = lane & 3;                                   \
    const int arow = (lane & 7) + ((lane >> 3) & 1) * 8;                      \
    const int acol = (lane >> 4) * 8;                                         \
    const int brow = ((lane >> 4) & 1) * 8 + (lane & 7);                      \
    const int bcol = ((lane >> 3) & 1) * 8;                                   \
    const int r4 = tid >> 2, c4 = tid & 3;                                    \
    const uint32_t so = r4 * 80 + c4 * 16;                                    \
    float acc[4][4][4];                                                       \
    _Pragma("unroll")                                                         \
    for (int mt = 0; mt < 4; mt++)                                            \
        _Pragma("unroll")                                                     \
        for (int nt = 0; nt < 4; nt++)                                        \
            _Pragma("unroll")                                                 \
            for (int e = 0; e < 4; e++) acc[mt][nt][e] = 0.f;                 \
    const int n_tiles = K >> 5;                                               \
    QLOAD(0);                                                                 \
    QLOAD(1);                                                                 \
    for (int t = 0; t < n_tiles; t++) {                                       \
        if (t + 2 < n_tiles) {                                                \
            QLOAD(t + 2);                                                     \
            asm volatile("cp.async.wait_group 2;");                           \
        } else if (t + 1 < n_tiles) {                                         \
            asm volatile("cp.async.wait_group 1;");                           \
        } else {                                                              \
            asm volatile("cp.async.wait_group 0;");                           \
        }                                                                     \
        __syncthreads();                                                      \
        const uint32_t sb = sbase + (t % 3) * QSTG;                           \
        _Pragma("unroll")                                                     \
        for (int kk = 0; kk < 2; kk++) {                                      \
            const int kc = kk * 16;                                           \
            uint32_t ah[4][4], bh[2][4], bl[2][4];                            \
            _Pragma("unroll")                                                 \
            for (int mt = 0; mt < 4; mt++) {                                  \
                uint32_t ad = sb + QS_AH +                                    \
                              ((wm + mt * 16 + arow) * HS + kc + acol) * 2;   \
                LDSM_X4(ah[mt], ad);                                          \
            }                                                                 \
            _Pragma("unroll")                                                 \
            for (int a2 = 0; a2 < 2; a2++) {                                  \
                uint32_t bd = sb + QS_BH +                                    \
                              ((wn + a2 * 16 + brow) * HS + kc + bcol) * 2;   \
                LDSM_X4(bh[a2], bd);                                          \
                LDSM_X4(bl[a2], bd + (QS_BL - QS_BH));                        \
            }                                                                 \
            _Pragma("unroll")                                                 \
            for (int mt = 0; mt < 4; mt++)                                    \
                _Pragma("unroll")                                             \
                for (int nt = 0; nt < 4; nt++) {                              \
                    const int hi2 = nt >> 1, p = (nt & 1) * 2;                \
                    MMA_F16B(acc[mt][nt], ah[mt], bh[hi2][p], bh[hi2][p+1]);  \
                    MMA_F16B(acc[mt][nt], ah[mt], bl[hi2][p], bl[hi2][p+1]);  \
                }                                                             \
        }                                                                     \
        __syncthreads();                                                      \
    }                                                                         \
    _Pragma("unroll")                                                         \
    for (int mt = 0; mt < 4; mt++) {                                          \
        const int row = bm + wm + mt * 16 + g;                                \
        _Pragma("unroll")                                                     \
        for (int nt = 0; nt < 4; nt++) {                                      \
            const int col = bnL + wn + nt * 8 + tg * 2;                       \
            const float b0 = (biasptr)[col], b1 = (biasptr)[col + 1];         \
            float2 v0 = make_float2(acc[mt][nt][0] + b0, acc[mt][nt][1] + b1);\
            float2 v1 = make_float2(acc[mt][nt][2] + b0, acc[mt][nt][3] + b1);\
            *(float2*)((Yptr) + (size_t)row * D_MODEL + col) = v0;            \
            *(float2*)((Yptr) + (size_t)(row + 8) * D_MODEL + col) = v1;      \
        }                                                                     \
    }

#define QLOAD(t) do {                                                         \
        const uint32_t _sb = sbase + ((t) % 3) * QSTG;                        \
        const int _kb = (t) << 5;                                             \
        const size_t _ga0 = (size_t)(bm + r4) * K + _kb + c4 * 8;             \
        const size_t _ga1 = (size_t)(bm + 64 + r4) * K + _kb + c4 * 8;        \
        const size_t _gb0 = (size_t)(bnG + r4) * K + _kb + c4 * 8;            \
        const size_t _gb1 = (size_t)(bnG + 64 + r4) * K + _kb + c4 * 8;       \
        CP_ASYNC16(_sb + QS_AH + so,        Ahg + _ga0);                      \
        CP_ASYNC16(_sb + QS_AH + so + 5120, Ahg + _ga1);                      \
        CP_ASYNC16(_sb + QS_BH + so,        Bhg + _gb0);                      \
        CP_ASYNC16(_sb + QS_BH + so + 5120, Bhg + _gb1);                      \
        CP_ASYNC16(_sb + QS_BL + so,        Blg + _gb0);                      \
        CP_ASYNC16(_sb + QS_BL + so + 5120, Blg + _gb1);                      \
        asm volatile("cp.async.commit_group;");                               \
    } while (0)

__global__ __launch_bounds__(256, 2) void gemm_qkv2(
    const __half* __restrict__ Ahg,
    const __half* __restrict__ Bhg, const __half* __restrict__ Blg,
    const float* __restrict__ bk, const float* __restrict__ bq,
    const float* __restrict__ bv,
    float* __restrict__ Yk, float* __restrict__ Yq, float* __restrict__ Yv,
    int M, int K)
{
    const int bnG = blockIdx.x * 128;
    const int seg = bnG >> 10;
    const int bnL = bnG & 1023;
    const float* bias = (seg == 0) ? bk : (seg == 1) ? bq : bv;
    float* Y = (seg == 0) ? Yk : (seg == 1) ? Yq : Yv;
    GEMM2_BODY(Y, bias)
}

__global__ __launch_bounds__(256, 2) void gemm_h2b(
    const __half* __restrict__ Ahg,
    const __half* __restrict__ Bhg, const __half* __restrict__ Blg,
    const float* __restrict__ bias, float* __restrict__ Y,
    int M, int K)
{
    const int bnG = blockIdx.x * 128;
    const int bnL = bnG;
    GEMM2_BODY(Y, bias)
}
#undef QLOAD

/* -------- prep8: 512 threads, 2 channels/thread (round-13 version) ---------- */
__global__ __launch_bounds__(512, 2) void prep8(
    const float* __restrict__ x,
    const float* __restrict__ Wbeta, const float* __restrict__ bbeta,
    const float* __restrict__ ck, const float* __restrict__ cq,
    const float* __restrict__ cv)
{
    __shared__ float xs[8 * D_MODEL];
    __shared__ float eta_s[8][N_HEADS];

    const int bid = blockIdx.x;
    const int b = bid >> 8;
    const int l0 = (bid & 255) * 8;
    const int tid = threadIdx.x;
    const int d = tid * 2;
    const int h = tid >> 5;
    const int lane = tid & 31;
    const int w = tid >> 5;

#pragma unroll
    for (int i = 0; i < 4; i++) {
        int idx = i * 512 + tid;
        int t = idx >> 8, c = idx & 255;
        ((float4*)xs)[t * 256 + c] =
            *(const float4*)(x + ((size_t)(b * L_DIM + l0 + t)) * D_MODEL + c * 4);
    }
    __syncthreads();

    {
        const int t = w >> 1;
        const int hb0 = (w & 1) * 8;
        const float* xr = xs + t * D_MODEL;
#pragma unroll
        for (int hh = 0; hh < 8; hh++) {
            int hb = hb0 + hh;
            float s = 0.f;
            const float* wb = Wbeta + hb * D_MODEL;
            for (int k = lane * 4; k < D_MODEL; k += 128) {
                float4 xv = *(const float4*)(xr + k);
                float4 wv = *(const float4*)(wb + k);
                s += xv.x * wv.x + xv.y * wv.y + xv.z * wv.z + xv.w * wv.w;
            }
#pragma unroll
            for (int o = 16; o > 0; o >>= 1) s += __shfl_down_sync(0xffffffffu, s, o);
            if (lane == 0) eta_s[t][hb] = 1.f / (1.f + __expf(-(s + bbeta[hb])));
        }
    }

    float4 cwk[2], cwq[2], cwv[2];
#pragma unroll
    for (int c = 0; c < 2; c++) {
        cwk[c] = ((const float4*)ck)[d + c];
        cwq[c] = ((const float4*)cq)[d + c];
        cwv[c] = ((const float4*)cv)[d + c];
    }

    float2 wk[4], wq[4], wv[4];
#pragma unroll
    for (int j = 0; j < 3; j++) {
        int ls = l0 - 3 + j;
        if (ls >= 0) {
            size_t base = ((size_t)(b * L_DIM + ls)) * D_MODEL + d;
            wk[j] = *(const float2*)&g_kpre[base];
            wq[j] = *(const float2*)&g_qpre[base];
            wv[j] = *(const float2*)&g_vpre[base];
        } else {
            wk[j] = wq[j] = wv[j] = make_float2(0.f, 0.f);
        }
    }
    __syncthreads();

#pragma unroll
    for (int t = 0; t < 8; t++) {
        {
            size_t base = ((size_t)(b * L_DIM + l0 + t)) * D_MODEL + d;
            wk[(t + 3) & 3] = *(const float2*)&g_kpre[base];
            wq[(t + 3) & 3] = *(const float2*)&g_qpre[base];
            wv[(t + 3) & 3] = *(const float2*)&g_vpre[base];
        }
        float ak0 = 0.f, ak1 = 0.f, aq0 = 0.f, aq1 = 0.f, av0 = 0.f, av1 = 0.f;
#pragma unroll
        for (int j = 0; j < 4; j++) {
            const int sl = (t + j) & 3;
            float wk0 = ((const float*)&cwk[0])[j], wk1 = ((const float*)&cwk[1])[j];
            float wq0 = ((const float*)&cwq[0])[j], wq1 = ((const float*)&cwq[1])[j];
            float wv0 = ((const float*)&cwv[0])[j], wv1 = ((const float*)&cwv[1])[j];
            ak0 += wk[sl].x * wk0; ak1 += wk[sl].y * wk1;
            aq0 += wq[sl].x * wq0; aq1 += wq[sl].y * wq1;
            av0 += wv[sl].x * wv0; av1 += wv[sl].y * wv1;
        }
        float sk = ak0 * ak0 + ak1 * ak1;
        float sq = aq0 * aq0 + aq1 * aq1;
#pragma unroll
        for (int o = 16; o > 0; o >>= 1) {
            sk += __shfl_xor_sync(0xffffffffu, sk, o);
            sq += __shfl_xor_sync(0xffffffffu, sq, o);
        }
        const float rkn = 1.f / (sqrtf(sk) + 1e-6f);
        const float rqn = 1.f / (sqrtf(sq) + 1e-6f);
        const float e = eta_s[t][h];

        float kn0 = ak0 * rkn, kn1 = ak1 * rkn;
        float qn0 = aq0 * rqn, qn1 = aq1 * rqn;
        float sv0 = av0 / (1.f + __expf(-av0));
        float sv1 = av1 / (1.f + __expf(-av1));
        size_t obase = (((size_t)(b * N_HEADS + h)) * L_DIM + l0 + t) * D_HEAD + (d & 63);
        *(float2*)&g_kn[obase] = make_float2(kn0, kn1);
        *(float2*)&g_qn[obase] = make_float2(qn0, qn1);
        *(float2*)&g_vs[obase] = make_float2(e * sv0, e * sv1);
        *(float2*)&g_bb[obase] = make_float2(e * kn0, e * kn1);
    }
}

/* ---------------- chunked o2b weighted delta-rule scan (round-13 version) --- */
#define SPLIT_ST(ah_, al_, idx_, val_) do {                                   \
        __half _hh = __float2half_rn(val_);                                   \
        (ah_)[idx_] = _hh;                                                    \
        (al_)[idx_] = __float2half_rn((val_) - __half2float(_hh));            \
    } while (0)

#define DSM_BYTES ((2 * 64 * FS + 3 * 64 * HSX + 512 + 256) * 4 +             \
                   (10 * F16T + 8 * F16H) * 2)

__global__ __launch_bounds__(256) void delta_kernel()
{
    extern __shared__ float smd[];
    float* Ts   = smd;
    float* Qk   = Ts + 64 * FS;
    float* Wt   = Qk + 64 * FS;
    float* Wa   = Wt + 64 * HSX;
    float* Us   = Wa + 64 * HSX;
    float* invD = Us + 64 * HSX;
    float* Mb   = invD + 512;
    __half* Kh   = (__half*)(Mb + 256);
    __half* Kl   = Kh  + F16T;
    __half* Qh   = Kl  + F16T;
    __half* Ql   = Qh  + F16T;
    __half* Bh2  = Ql  + F16T;
    __half* Bl2  = Bh2 + F16T;
    __half* KTh  = Bl2 + F16T;
    __half* KTl  = KTh + F16T;
    __half* Sh   = KTl + F16T;
    __half* Sl   = Sh  + F16T;
    __half* WtTh = Sl  + F16T;
    __half* WtTl = WtTh + F16H;
    __half* WaTh = WtTl + F16H;
    __half* WaTl = WaTh + F16H;
    __half* UTh  = WaTl + F16H;
    __half* UTl  = UTh + F16H;
    __half* UwTh = UTl + F16H;
    __half* UwTl = UwTh + F16H;

    const int tid = threadIdx.x;
    const int lane = tid & 31, w = tid >> 5;
    const int g = lane >> 2, tg = lane & 3;
    const int arow = (lane & 7) + ((lane >> 3) & 1) * 8;
    const int acol = (lane >> 4) * 8;
    const int brow = ((lane >> 4) & 1) * 8 + (lane & 7);
    const int bcol = ((lane >> 3) & 1) * 8;

    const int pair = blockIdx.x >> 1;
    const int half = blockIdx.x & 1;
    const int col0 = half * 32;
    const int b = pair >> 4, h = pair & 15;

    for (int i = tid; i < 64 * HSX; i += 256) { Wt[i] = 0.f; Wa[i] = 0.f; }

    const size_t pbase = (size_t)pair * L_DIM * D_HEAD;
    const uint32_t khB = smem_u32(Kh), klB = smem_u32(Kl);

    for (int chunk = 0; chunk < N_CHUNK; chunk++) {
        __syncthreads();
        const size_t cb = pbase + (size_t)chunk * 64 * D_HEAD;
        for (int i2 = tid; i2 < 4096; i2 += 256) {
            int r = i2 >> 6, c = i2 & 63;
            float kv = g_kn[cb + i2];
            float qv = g_qn[cb + i2];
            float bv = g_bb[cb + i2];
            SPLIT_ST(Kh, Kl, r * HX + c, kv);
            SPLIT_ST(KTh, KTl, c * HX + r, kv);
            SPLIT_ST(Qh, Ql, r * HX + c, qv);
            SPLIT_ST(Bh2, Bl2, r * HX + c, bv);
        }
        for (int i2 = tid; i2 < 2048; i2 += 256) {
            int r = i2 >> 5, c = i2 & 31;
            Us[r * HSX + c] = g_vs[cb + r * 64 + col0 + c];
        }
        for (int i2 = tid; i2 < 2048; i2 += 256) {
            int m = i2 >> 5, n = i2 & 31;
            SPLIT_ST(WtTh, WtTl, n * HX + m, Wt[m * HSX + n]);
            SPLIT_ST(WaTh, WaTl, n * HX + m, Wa[m * HSX + n]);
        }
        __syncthreads();

        const float ts    = (float)(chunk * 64);
        const float tri0  = 0.5f * (1.f + ts) * ts;
        const float denw  = 0.5f * (65.f + ts) * (64.f + ts);
        const float Ssum  = 64.f * ts + 2080.f;
        const float coef1 = (ts / (ts + 64.f)) * ((1.f + ts) / (ts + 65.f));
        const float coef2 = (64.f / (ts + 64.f)) * ((2.f * ts + 65.f) / (ts + 65.f));

        /* PASS 1a: [B;Q] @ K^T -> T (warps 0-3, tril) / QK (warps 4-7) */
        {
            const uint32_t ahB = smem_u32((w < 4) ? Bh2 : Qh);
            const uint32_t alB = smem_u32((w < 4) ? Bl2 : Ql);
            const int r0 = (w & 3) * 16;
            float acc[8][4];
#pragma unroll
            for (int j = 0; j < 8; j++)
#pragma unroll
                for (int e = 0; e < 4; e++) acc[j][e] = 0.f;

#pragma unroll
            for (int ks = 0; ks < 4; ks++) {
                const int kc = ks * 16;
                uint32_t ah[4], al[4], bh[4][4], bl[4][4];
                const uint32_t aoff = ((r0 + arow) * HX + kc + acol) * 2;
                LDSM_X4(ah, ahB + aoff);
                LDSM_X4(al, alB + aoff);
#pragma unroll
                for (int nt = 0; nt < 4; nt++) {
                    const uint32_t boff = ((nt * 16 + brow) * HX + kc + bcol) * 2;
                    LDSM_X4(bh[nt], khB + boff);
                    LDSM_X4(bl[nt], klB + boff);
                }
#pragma unroll
                for (int j = 0; j < 8; j++) {
                    const int grp = j >> 1, p = (j & 1) * 2;
                    MMA_F16B(acc[j], ah, bh[grp][p], bh[grp][p + 1]);
                    MMA_F16B(acc[j], ah, bl[grp][p], bl[grp][p + 1]);
                    MMA_F16B(acc[j], al, bh[grp][p], bh[grp][p + 1]);
                }
            }
            if (w < 4) {
#pragma unroll
                for (int j = 0; j < 8; j++) {
                    const int C = j * 8 + tg * 2;
                    const int R1 = r0 + g, R2 = r0 + g + 8;
                    Ts[R1 * FS + C]     = (R1 > C)     ? acc[j][0] : 0.f;
                    Ts[R1 * FS + C + 1] = (R1 > C + 1) ? acc[j][1] : 0.f;
                    Ts[R2 * FS + C]     = (R2 > C)     ? acc[j][2] : 0.f;
                    Ts[R2 * FS + C + 1] = (R2 > C + 1) ? acc[j][3] : 0.f;
                }
            } else {
#pragma unroll
                for (int j = 0; j < 8; j++) {
                    const int C = j * 8 + tg * 2;
                    const int R1 = r0 + g, R2 = r0 + g + 8;
                    Qk[R1 * FS + C]     = acc[j][0];
                    Qk[R1 * FS + C + 1] = acc[j][1];
                    Qk[R2 * FS + C]     = acc[j][2];
                    Qk[R2 * FS + C + 1] = acc[j][3];
                }
            }
        }

        /* PASS 1b: RHS = V - B @ Wt */
        {
            const uint32_t b2h = smem_u32(Bh2), b2l = smem_u32(Bl2);
            const uint32_t wth = smem_u32(WtTh), wtl = smem_u32(WtTl);
            const int bm0 = (w & 3) * 16;
            const int bn0 = (w >> 2) * 16;
            float accB[2][4];
#pragma unroll
            for (int nt = 0; nt < 2; nt++)
#pragma unroll
                for (int e = 0; e < 4; e++) accB[nt][e] = 0.f;
#pragma unroll
            for (int ks = 0; ks < 4; ks++) {
                const int kc = ks * 16;
                uint32_t ah[4], al[4], bh[4], bl[4];
                const uint32_t aoff = ((bm0 + arow) * HX + kc + acol) * 2;
                LDSM_X4(ah, b2h + aoff);
                LDSM_X4(al, b2l + aoff);
                const uint32_t boff = ((bn0 + brow) * HX + kc + bcol) * 2;
                LDSM_X4(bh, wth + boff);
                LDSM_X4(bl, wtl + boff);
#pragma unroll
                for (int nt = 0; nt < 2; nt++) {
                    const int p = nt * 2;
                    MMA_F16B(accB[nt], ah, bh[p], bh[p + 1]);
                    MMA_F16B(accB[nt], ah, bl[p], bl[p + 1]);
                    MMA_F16B(accB[nt], al, bh[p], bh[p + 1]);
                }
            }
#pragma unroll
            for (int nt = 0; nt < 2; nt++) {
                const int col = bn0 + nt * 8 + tg * 2;
                const int R1 = bm0 + g, R2 = bm0 + g + 8;
                Us[R1 * HSX + col]     -= accB[nt][0];
                Us[R1 * HSX + col + 1] -= accB[nt][1];
                Us[R2 * HSX + col]     -= accB[nt][2];
                Us[R2 * HSX + col + 1] -= accB[nt][3];
            }
        }
        __syncthreads();

        /* C0: invert the 8 unit-lower 8x8 diagonal blocks */
        if (tid < 64) {
            const int blk = tid >> 3, c = tid & 7;
            const int r0 = blk * 8;
            float xcol[8];
#pragma unroll
            for (int r = 0; r < 8; r++) {
                float s = (r == c) ? 1.f : 0.f;
                for (int k2 = c; k2 < r; k2++)
                    s -= Ts[(r0 + r) * FS + r0 + k2] * xcol[k2];
                xcol[r] = s;
            }
#pragma unroll
            for (int r = 0; r < 8; r++) invD[(r0 + r) * 8 + c] = xcol[r];
        }
        __syncthreads();

        /* C: blocked forward substitution (I+T) U = RHS */
        {
            const int cc = tid & 31, rr = tid >> 5;
            for (int ib = 0; ib < 8; ib++) {
                const int r0 = ib * 8;
                float s = 0.f;
                for (int j = 0; j < r0; j++)
                    s += Ts[(r0 + rr) * FS + j] * Us[j * HSX + cc];
                float rhs = Us[(r0 + rr) * HSX + cc] - s;
                Mb[rr * 32 + cc] = rhs;
                __syncthreads();
                s = rhs;
                for (int k2 = 0; k2 < rr; k2++)
                    s += invD[(r0 + rr) * 8 + k2] * Mb[k2 * 32 + cc];
                Us[(r0 + rr) * HSX + cc] = s;
                __syncthreads();
            }
        }

        /* conversions: S = weights o QK; U^T and (U*w)^T in fp16 hi/lo */
        for (int i2 = tid; i2 < 4096; i2 += 256) {
            int r = i2 >> 6, c = i2 & 63;
            float rr2 = (float)r;
            float cs_r = (rr2 + 1.f) * ts + 0.5f * (rr2 + 1.f) * (rr2 + 2.f);
            float rdiv = 1.f / (tri0 + cs_r);
            float kf = (float)c;
            float csk_m = kf * ts + 0.5f * kf * (kf + 1.f);
            float num = cs_r - csk_m;
            float sfac = (num >= 0.f) ? num * rdiv : 0.f;
            float sv = sfac * Qk[r * FS + c];
            SPLIT_ST(Sh, Sl, r * HX + c, sv);
        }
        for (int i2 = tid; i2 < 2048; i2 += 256) {
            int c = i2 >> 6, r = i2 & 63;
            float u = Us[r * HSX + c];
            float rr2 = (float)r;
            float idxr = ts + rr2 + 1.f;
            float csrr = (rr2 + 1.f) * ts + 0.5f * (rr2 + 1.f) * (rr2 + 2.f);
            float wr = (idxr + Ssum - csrr) / denw;
            SPLIT_ST(UTh, UTl, c * HX + r, u);
            SPLIT_ST(UwTh, UwTl, c * HX + r, u * wr);
        }
        __syncthreads();

        /* PASS 2: warps 0-3 -> O (D + F); warps 4-7 -> H (W updates) */
        if (w < 4) {
            const int r0 = w * 16;
            const uint32_t qhB = smem_u32(Qh), qlB = smem_u32(Ql);
            const uint32_t shB = smem_u32(Sh), slB = smem_u32(Sl);
            const uint32_t wah = smem_u32(WaTh), wal = smem_u32(WaTl);
            const uint32_t wth = smem_u32(WtTh), wtl = smem_u32(WtTl);
            const uint32_t uth = smem_u32(UTh), utl = smem_u32(UTl);
            float aA[4][4], aT[4][4], aF[4][4];
#pragma unroll
            for (int nt = 0; nt < 4; nt++)
#pragma unroll
                for (int e = 0; e < 4; e++) { aA[nt][e] = 0.f; aT[nt][e] = 0.f; aF[nt][e] = 0.f; }

#pragma unroll
            for (int ks = 0; ks < 4; ks++) {
                const int kc = ks * 16;
                const uint32_t aoff = ((r0 + arow) * HX + kc + acol) * 2;
                uint32_t qh[4], ql[4], sh[4], sl[4];
                LDSM_X4(qh, qhB + aoff);
                LDSM_X4(ql, qlB + aoff);
                LDSM_X4(sh, shB + aoff);
                LDSM_X4(sl, slB + aoff);
                uint32_t bwa[2][4], bwa2[2][4], bwt[2][4], bwt2[2][4], bu[2][4], bu2[2][4];
#pragma unroll
                for (int a2 = 0; a2 < 2; a2++) {
                    const uint32_t boff = ((a2 * 16 + brow) * HX + kc + bcol) * 2;
                    LDSM_X4(bwa[a2], wah + boff);
                    LDSM_X4(bwa2[a2], wal + boff);
                    LDSM_X4(bwt[a2], wth + boff);
                    LDSM_X4(bwt2[a2], wtl + boff);
                    LDSM_X4(bu[a2], uth + boff);
                    LDSM_X4(bu2[a2], utl + boff);
                }
#pragma unroll
                for (int nt = 0; nt < 4; nt++) {
                    const int grp = nt >> 1, p = (nt & 1) * 2;
                    MMA_F16B(aA[nt], qh, bwa[grp][p], bwa[grp][p + 1]);
                    MMA_F16B(aA[nt], qh, bwa2[grp][p], bwa2[grp][p + 1]);
                    MMA_F16B(aA[nt], ql, bwa[grp][p], bwa[grp][p + 1]);
                    MMA_F16B(aT[nt], qh, bwt[grp][p], bwt[grp][p + 1]);
                    MMA_F16B(aT[nt], qh, bwt2[grp][p], bwt2[grp][p + 1]);
                    MMA_F16B(aT[nt], ql, bwt[grp][p], bwt[grp][p + 1]);
                    MMA_F16B(aF[nt], sh, bu[grp][p], bu[grp][p + 1]);
                    MMA_F16B(aF[nt], sh, bu2[grp][p], bu2[grp][p + 1]);
                    MMA_F16B(aF[nt], sl, bu[grp][p], bu[grp][p + 1]);
                }
            }
            const int r1 = r0 + g, r2 = r1 + 8;
            float f1 = (float)r1, f2 = (float)r2;
            float cs1 = (f1 + 1.f) * ts + 0.5f * (f1 + 1.f) * (f1 + 2.f);
            float cs2 = (f2 + 1.f) * ts + 0.5f * (f2 + 1.f) * (f2 + 2.f);
            float ar1 = tri0 / (tri0 + cs1);
            float ar2 = tri0 / (tri0 + cs2);
#pragma unroll
            for (int nt = 0; nt < 4; nt++) {
                const int cg = h * 64 + col0 + nt * 8 + tg * 2;
                int l1 = chunk * 64 + r1, l2 = chunk * 64 + r2;
                float2 v1 = make_float2(
                    ar1 * aA[nt][0] + (1.f - ar1) * aT[nt][0] + aF[nt][0],
                    ar1 * aA[nt][1] + (1.f - ar1) * aT[nt][1] + aF[nt][1]);
                float2 v2 = make_float2(
                    ar2 * aA[nt][2] + (1.f - ar2) * aT[nt][2] + aF[nt][2],
                    ar2 * aA[nt][3] + (1.f - ar2) * aT[nt][3] + aF[nt][3]);
                *(float2*)&g_o[((size_t)(b * L_DIM + l1)) * D_MODEL + cg] = v1;
                *(float2*)&g_o[((size_t)(b * L_DIM + l2)) * D_MODEL + cg] = v2;
            }
        } else {
            const int m0 = (w - 4) * 16;
            const uint32_t kth = smem_u32(KTh), ktl = smem_u32(KTl);
            const uint32_t uth = smem_u32(UTh), utl = smem_u32(UTl);
            const uint32_t uwh = smem_u32(UwTh), uwl = smem_u32(UwTl);
            float p1a[4][4], p2a[4][4];
#pragma unroll
            for (int nt = 0; nt < 4; nt++)
#pragma unroll
                for (int e = 0; e < 4; e++) { p1a[nt][e] = 0.f; p2a[nt][e] = 0.f; }

#pragma unroll
            for (int ks = 0; ks < 4; ks++) {
                const int kc = ks * 16;
                const uint32_t aoff = ((m0 + arow) * HX + kc + acol) * 2;
                uint32_t kh2[4], kl2[4];
                LDSM_X4(kh2, kth + aoff);
                LDSM_X4(kl2, ktl + aoff);
                uint32_t bu[2][4], bu2[2][4], bw[2][4], bw2[2][4];
#pragma unroll
                for (int a2 = 0; a2 < 2; a2++) {
                    const uint32_t boff = ((a2 * 16 + brow) * HX + kc + bcol) * 2;
                    LDSM_X4(bu[a2], uth + boff);
                    LDSM_X4(bu2[a2], utl + boff);
                    LDSM_X4(bw[a2], uwh + boff);
                    LDSM_X4(bw2[a2], uwl + boff);
                }
#pragma unroll
                for (int nt = 0; nt < 4; nt++) {
                    const int grp = nt >> 1, p = (nt & 1) * 2;
                    MMA_F16B(p1a[nt], kh2, bu[grp][p], bu[grp][p + 1]);
                    MMA_F16B(p1a[nt], kh2, bu2[grp][p], bu2[grp][p + 1]);
                    MMA_F16B(p1a[nt], kl2, bu[grp][p], bu[grp][p + 1]);
                    MMA_F16B(p2a[nt], kh2, bw[grp][p], bw[grp][p + 1]);
                    MMA_F16B(p2a[nt], kh2, bw2[grp][p], bw2[grp][p + 1]);
                    MMA_F16B(p2a[nt], kl2, bw[grp][p], bw[grp][p + 1]);
                }
            }
            const int m1 = m0 + g, m2 = m1 + 8;
#pragma unroll
            for (int nt = 0; nt < 4; nt++) {
                const int n = nt * 8 + tg * 2;
#pragma unroll
                for (int cc2 = 0; cc2 < 2; cc2++) {
                    int i1 = m1 * HSX + n + cc2;
                    float wo = Wt[i1];
                    Wa[i1] = coef1 * Wa[i1] + coef2 * wo + p2a[nt][cc2];
                    Wt[i1] = wo + p1a[nt][cc2];
                    int i2x = m2 * HSX + n + cc2;
                    wo = Wt[i2x];
                    Wa[i2x] = coef1 * Wa[i2x] + coef2 * wo + p2a[nt][2 + cc2];
                    Wt[i2x] = wo + p1a[nt][2 + cc2];
                }
            }
        }
    }
}

/* -------- RMS norm over head dim + fp16 (hi only) for final 2-pass GEMM ----- */
__global__ __launch_bounds__(256) void rms_split(const float* __restrict__ rms_w)
{
    const int bl = blockIdx.x, tid = threadIdx.x;
    float4 v = ((const float4*)g_o)[(size_t)bl * 256 + tid];
    float ss = v.x * v.x + v.y * v.y + v.z * v.z + v.w * v.w;
#pragma unroll
    for (int o = 8; o > 0; o >>= 1) ss += __shfl_xor_sync(0xffffffffu, ss, o);
    float scale = rsqrtf(ss * (1.f / 64.f) + 1e-6f);
    float4 rw = ((const float4*)rms_w)[tid & 15];
    float a0 = v.x * scale * rw.x, a1 = v.y * scale * rw.y;
    float a2 = v.z * scale * rw.z, a3 = v.w * scale * rw.w;
    __half2 h01 = __floats2half2_rn(a0, a1);
    __half2 h23 = __floats2half2_rn(a2, a3);
    ((uint2*)g_oh)[(size_t)bl * 256 + tid] = make_uint2(*(uint32_t*)&h01, *(uint32_t*)&h23);
}

/* ------------------------------- launcher ----------------------------------*/
extern "C" void kernel_launch(void* const* d_in, const int* in_sizes, int n_in,
                              void* d_out, int out_size)
{
    (void)in_sizes; (void)n_in; (void)out_size;
    const float* x     = (const float*)d_in[0];
    const float* Wk    = (const float*)d_in[1];
    const float* bk    = (const float*)d_in[2];
    const float* Wq    = (const float*)d_in[3];
    const float* bq    = (const float*)d_in[4];
    const float* Wv    = (const float*)d_in[5];
    const float* bv    = (const float*)d_in[6];
    const float* Wbeta = (const float*)d_in[7];
    const float* bbeta = (const float*)d_in[8];
    const float* ck    = (const float*)d_in[9];
    const float* cq    = (const float*)d_in[10];
    const float* cv    = (const float*)d_in[11];
    const float* rms_w = (const float*)d_in[12];
    const float* Wout  = (const float*)d_in[13];
    const float* bout  = (const float*)d_in[14];
    float* out = (float*)d_out;

    float *kpre, *qpre, *vpre;
    __half *xh, *oh, *wsh, *wsl;
    cudaGetSymbolAddress((void**)&kpre, g_kpre);
    cudaGetSymbolAddress((void**)&qpre, g_qpre);
    cudaGetSymbolAddress((void**)&vpre, g_vpre);
    cudaGetSymbolAddress((void**)&xh, g_xh);
    cudaGetSymbolAddress((void**)&oh, g_oh);
    cudaGetSymbolAddress((void**)&wsh, g_wsh);
    cudaGetSymbolAddress((void**)&wsl, g_wsl);

    split_hi<<<(ML * D_MODEL / 4 + 255) / 256, 256>>>(
        (const float4*)x, (uint2*)xh, ML * D_MODEL / 4);
    split_w4<<<(4 * DD / 4) / 256, 256>>>(
        (const float4*)Wk, (const float4*)Wq, (const float4*)Wv,
        (const float4*)Wout, (uint2*)wsh, (uint2*)wsl);

    cudaFuncSetAttribute(gemm_qkv2, cudaFuncAttributeMaxDynamicSharedMemorySize,
                         QSM_BYTES);
    cudaFuncSetAttribute(gemm_h2b, cudaFuncAttributeMaxDynamicSharedMemorySize,
                         QSM_BYTES);

    gemm_qkv2<<<dim3(24, 64), 256, QSM_BYTES>>>(
        xh, wsh, wsl, bk, bq, bv, kpre, qpre, vpre, ML, D_MODEL);

    prep8<<<B_DIM * (L_DIM / 8), 512>>>(x, Wbeta, bbeta, ck, cq, cv);

    cudaFuncSetAttribute(delta_kernel, cudaFuncAttributeMaxDynamicSharedMemorySize,
                         DSM_BYTES);
    delta_kernel<<<2 * N_PAIR, 256, DSM_BYTES>>>();

    rms_split<<<ML, 256>>>(rms_w);

    gemm_h2b<<<dim3(8, 64), 256, QSM_BYTES>>>(
        oh, wsh + 3 * DD, wsl + 3 * DD, bout, out, ML, D_MODEL);
}

// round 16
// speedup vs baseline: 1.0273x; 1.0129x over previous
#include <cuda_runtime.h>
#include <cuda_fp16.h>
#include <math.h>
#include <stdint.h>

#define B_DIM   4
#define L_DIM   2048
#define D_MODEL 1024
#define N_HEADS 16
#define D_HEAD  64
#define ML      (B_DIM * L_DIM)
#define N_PAIR  (B_DIM * N_HEADS)
#define N_CHUNK (L_DIM / 64)
#define DD      (D_MODEL * D_MODEL)
#define FS      65                       /* full fp32 smem stride */
#define HSX     33                       /* half-width fp32 smem stride */
#define HX      72                       /* fp16 tile stride (halves) */
#define F16T    (64 * HX)
#define F16H    (32 * HX)

/* ---------------- scratch (device globals; no runtime alloc) ---------------- */
__device__ float  g_kpre[ML * D_MODEL];
__device__ float  g_qpre[ML * D_MODEL];
__device__ float  g_vpre[ML * D_MODEL];
__device__ float  g_kn  [ML * D_MODEL];
__device__ float  g_qn  [ML * D_MODEL];
__device__ float  g_vs  [ML * D_MODEL];
__device__ float  g_bb  [ML * D_MODEL];
__device__ float  g_o   [ML * D_MODEL];
__device__ __half g_xh  [ML * D_MODEL];
__device__ __half g_oh  [ML * D_MODEL];
__device__ __half g_wsh [4 * DD];
__device__ __half g_wsl [4 * DD];

/* ---------------- fp32 -> fp16 splits, vectorized --------------------------- */
__device__ __forceinline__ void split4(float4 v, uint2& hi, uint2& lo) {
    __half2 h01 = __floats2half2_rn(v.x, v.y);
    __half2 h23 = __floats2half2_rn(v.z, v.w);
    __half2 l01 = __floats2half2_rn(v.x - __low2float(h01), v.y - __high2float(h01));
    __half2 l23 = __floats2half2_rn(v.z - __low2float(h23), v.w - __high2float(h23));
    hi = make_uint2(*(uint32_t*)&h01, *(uint32_t*)&h23);
    lo = make_uint2(*(uint32_t*)&l01, *(uint32_t*)&l23);
}

__global__ __launch_bounds__(256) void split_hi(
    const float4* __restrict__ src, uint2* __restrict__ hi, int n4)
{
    int i = blockIdx.x * blockDim.x + threadIdx.x;
    if (i >= n4) return;
    float4 v = src[i];
    __half2 h01 = __floats2half2_rn(v.x, v.y);
    __half2 h23 = __floats2half2_rn(v.z, v.w);
    hi[i] = make_uint2(*(uint32_t*)&h01, *(uint32_t*)&h23);
}

__global__ __launch_bounds__(256) void split_w4(
    const float4* __restrict__ w0, const float4* __restrict__ w1,
    const float4* __restrict__ w2, const float4* __restrict__ w3,
    uint2* __restrict__ hi, uint2* __restrict__ lo)
{
    int i = blockIdx.x * blockDim.x + threadIdx.x;
    int seg = i >> 18;
    int off = i & ((DD / 4) - 1);
    const float4* src = (seg == 0) ? w0 : (seg == 1) ? w1 : (seg == 2) ? w2 : w3;
    uint2 h, l;
    split4(src[off], h, l);
    hi[i] = h; lo[i] = l;
}

/* =================== tensor-core GEMM machinery (FP16) ====================== */
#define HS      40

__device__ __forceinline__ uint32_t smem_u32(const void* p) {
    uint32_t a;
    asm("{ .reg .u64 t; cvta.to.shared.u64 t, %1; cvt.u32.u64 %0, t; }"
        : "=r"(a) : "l"(p));
    return a;
}

#define LDSM_X4(r, a)                                                         \
    asm volatile("ldmatrix.sync.aligned.m8n8.x4.shared.b16 "                  \
                 "{%0,%1,%2,%3}, [%4];"                                       \
                 : "=r"((r)[0]), "=r"((r)[1]), "=r"((r)[2]), "=r"((r)[3])     \
                 : "r"(a))

#define MMA_F16B(d, a, b0, b1)                                                \
    asm volatile(                                                             \
        "mma.sync.aligned.m16n8k16.row.col.f32.f16.f16.f32 "                  \
        "{%0,%1,%2,%3}, {%4,%5,%6,%7}, {%8,%9}, {%0,%1,%2,%3};"               \
        : "+f"(d[0]), "+f"(d[1]), "+f"(d[2]), "+f"(d[3])                      \
        : "r"(a[0]), "r"(a[1]), "r"(a[2]), "r"(a[3]), "r"(b0), "r"(b1))

#define CP_ASYNC16(sa, gp)                                                    \
    asm volatile("cp.async.cg.shared.global [%0], [%1], 16;"                  \
                 :: "r"(sa), "l"(gp))

/* ---------- 2-pass mainloop, CTA 128x128, 3-stage, ONE sync per k-tile ------ */
#define QS_AH   0
#define QS_BH   10240
#define QS_BL   20480
#define QSTG    30720
#define QSM_BYTES (3 * QSTG)

#define GEMM2_BODY(Yptr, biasptr)                                             \
    extern __shared__ char smg[];                                             \
    const uint32_t sbase = smem_u32(smg);                                     \
    const int tid = threadIdx.x;                                              \
    const int bm = blockIdx.y * 128;                                          \
    const int lane = tid & 31, w = tid >> 5;                                  \
    const int wm = (w >> 2) * 64, wn = (w & 3) * 32;                          \
    const int g = lane >> 2, tg = lane & 3;                                   \
    const int arow = (lane & 7) + ((lane >> 3) & 1) * 8;                      \
    const int acol = (lane >> 4) * 8;                                         \
    const int brow = ((lane >> 4) & 1) * 8 + (lane & 7);                      \
    const int bcol = ((lane >> 3) & 1) * 8;                                   \
    const int r4 = tid >> 2, c4 = tid & 3;                                    \
    const uint32_t so = r4 * 80 + c4 * 16;                                    \
    float acc[4][4][4];                                                       \
    _Pragma("unroll")                                                         \
    for (int mt = 0; mt < 4; mt++)                                            \
        _Pragma("unroll")                                                     \
        for (int nt = 0; nt < 4; nt++)                                        \
            _Pragma("unroll")                                                 \
            for (int e = 0; e < 4; e++) acc[mt][nt][e] = 0.f;                 \
    const int n_tiles = K >> 5;                                               \
    QLOAD(0);                                                                 \
    QLOAD(1);                                                                 \
    for (int t = 0; t < n_tiles; t++) {                                       \
        if (t + 1 < n_tiles) asm volatile("cp.async.wait_group 1;");          \
        else                 asm volatile("cp.async.wait_group 0;");          \
        __syncthreads();                                                      \
        if (t + 2 < n_tiles) QLOAD(t + 2);                                    \
        const uint32_t sb = sbase + (t % 3) * QSTG;                           \
        _Pragma("unroll")                                                     \
        for (int kk = 0; kk < 2; kk++) {                                      \
            const int kc = kk * 16;                                           \
            uint32_t ah[4][4], bh[2][4], bl[2][4];                            \
            _Pragma("unroll")                                                 \
            for (int mt = 0; mt < 4; mt++) {                                  \
                uint32_t ad = sb + QS_AH +                                    \
                              ((wm + mt * 16 + arow) * HS + kc + acol) * 2;   \
                LDSM_X4(ah[mt], ad);                                          \
            }                                                                 \
            _Pragma("unroll")                                                 \
            for (int a2 = 0; a2 < 2; a2++) {                                  \
                uint32_t bd = sb + QS_BH +                                    \
                              ((wn + a2 * 16 + brow) * HS + kc + bcol) * 2;   \
                LDSM_X4(bh[a2], bd);                                          \
                LDSM_X4(bl[a2], bd + (QS_BL - QS_BH));                        \
            }                                                                 \
            _Pragma("unroll")                                                 \
            for (int mt = 0; mt < 4; mt++)                                    \
                _Pragma("unroll")                                             \
                for (int nt = 0; nt < 4; nt++) {                              \
                    const int hi2 = nt >> 1, p = (nt & 1) * 2;                \
                    MMA_F16B(acc[mt][nt], ah[mt], bh[hi2][p], bh[hi2][p+1]);  \
                    MMA_F16B(acc[mt][nt], ah[mt], bl[hi2][p], bl[hi2][p+1]);  \
                }                                                             \
        }                                                                     \
    }                                                                         \
    _Pragma("unroll")                                                         \
    for (int mt = 0; mt < 4; mt++) {                                          \
        const int row = bm + wm + mt * 16 + g;                                \
        _Pragma("unroll")                                                     \
        for (int nt = 0; nt < 4; nt++) {                                      \
            const int col = bnL + wn + nt * 8 + tg * 2;                       \
            const float b0 = (biasptr)[col], b1 = (biasptr)[col + 1];         \
            float2 v0 = make_float2(acc[mt][nt][0] + b0, acc[mt][nt][1] + b1);\
            float2 v1 = make_float2(acc[mt][nt][2] + b0, acc[mt][nt][3] + b1);\
            *(float2*)((Yptr) + (size_t)row * D_MODEL + col) = v0;            \
            *(float2*)((Yptr) + (size_t)(row + 8) * D_MODEL + col) = v1;      \
        }                                                                     \
    }

#define QLOAD(t) do {                                                         \
        const uint32_t _sb = sbase + ((t) % 3) * QSTG;                        \
        const int _kb = (t) << 5;                                             \
        const size_t _ga0 = (size_t)(bm + r4) * K + _kb + c4 * 8;             \
        const size_t _ga1 = (size_t)(bm + 64 + r4) * K + _kb + c4 * 8;        \
        const size_t _gb0 = (size_t)(bnG + r4) * K + _kb + c4 * 8;            \
        const size_t _gb1 = (size_t)(bnG + 64 + r4) * K + _kb + c4 * 8;       \
        CP_ASYNC16(_sb + QS_AH + so,        Ahg + _ga0);                      \
        CP_ASYNC16(_sb + QS_AH + so + 5120, Ahg + _ga1);                      \
        CP_ASYNC16(_sb + QS_BH + so,        Bhg + _gb0);                      \
        CP_ASYNC16(_sb + QS_BH + so + 5120, Bhg + _gb1);                      \
        CP_ASYNC16(_sb + QS_BL + so,        Blg + _gb0);                      \
        CP_ASYNC16(_sb + QS_BL + so + 5120, Blg + _gb1);                      \
        asm volatile("cp.async.commit_group;");                               \
    } while (0)

__global__ __launch_bounds__(256, 2) void gemm_qkv2(
    const __half* __restrict__ Ahg,
    const __half* __restrict__ Bhg, const __half* __restrict__ Blg,
    const float* __restrict__ bk, const float* __restrict__ bq,
    const float* __restrict__ bv,
    float* __restrict__ Yk, float* __restrict__ Yq, float* __restrict__ Yv,
    int M, int K)
{
    const int bnG = blockIdx.x * 128;
    const int seg = bnG >> 10;
    const int bnL = bnG & 1023;
    const float* bias = (seg == 0) ? bk : (seg == 1) ? bq : bv;
    float* Y = (seg == 0) ? Yk : (seg == 1) ? Yq : Yv;
    GEMM2_BODY(Y, bias)
}

__global__ __launch_bounds__(256, 2) void gemm_h2b(
    const __half* __restrict__ Ahg,
    const __half* __restrict__ Bhg, const __half* __restrict__ Blg,
    const float* __restrict__ bias, float* __restrict__ Y,
    int M, int K)
{
    const int bnG = blockIdx.x * 128;
    const int bnL = bnG;
    GEMM2_BODY(Y, bias)
}
#undef QLOAD

/* -------- prep4: 4 tokens/CTA, 512 threads, 2 channels/thread --------------- */
__global__ __launch_bounds__(512, 2) void prep4(
    const float* __restrict__ x,
    const float* __restrict__ Wbeta, const float* __restrict__ bbeta,
    const float* __restrict__ ck, const float* __restrict__ cq,
    const float* __restrict__ cv)
{
    __shared__ float xs[4 * D_MODEL];
    __shared__ float eta_s[4][N_HEADS];

    const int bid = blockIdx.x;            /* 0..2047 */
    const int b = bid >> 9;                /* L/4 = 512 per batch */
    const int l0 = (bid & 511) * 4;
    const int tid = threadIdx.x;
    const int d = tid * 2;
    const int h = tid >> 5;
    const int lane = tid & 31;
    const int w = tid >> 5;

#pragma unroll
    for (int i = 0; i < 2; i++) {
        int idx = i * 512 + tid;           /* 1024 float4 total */
        int t = idx >> 8, c = idx & 255;
        ((float4*)xs)[t * 256 + c] =
            *(const float4*)(x + ((size_t)(b * L_DIM + l0 + t)) * D_MODEL + c * 4);
    }
    __syncthreads();

    /* beta: warp w -> token w>>2, heads (w&3)*4 .. +3 */
    {
        const int t = w >> 2;
        const int hb0 = (w & 3) * 4;
        const float* xr = xs + t * D_MODEL;
#pragma unroll
        for (int hh = 0; hh < 4; hh++) {
            int hb = hb0 + hh;
            float s = 0.f;
            const float* wb = Wbeta + hb * D_MODEL;
            for (int k = lane * 4; k < D_MODEL; k += 128) {
                float4 xv = *(const float4*)(xr + k);
                float4 wv = *(const float4*)(wb + k);
                s += xv.x * wv.x + xv.y * wv.y + xv.z * wv.z + xv.w * wv.w;
            }
#pragma unroll
            for (int o = 16; o > 0; o >>= 1) s += __shfl_down_sync(0xffffffffu, s, o);
            if (lane == 0) eta_s[t][hb] = 1.f / (1.f + __expf(-(s + bbeta[hb])));
        }
    }

    float4 cwk[2], cwq[2], cwv[2];
#pragma unroll
    for (int c = 0; c < 2; c++) {
        cwk[c] = ((const float4*)ck)[d + c];
        cwq[c] = ((const float4*)cq)[d + c];
        cwv[c] = ((const float4*)cv)[d + c];
    }

    float2 wk[4], wq[4], wv[4];
#pragma unroll
    for (int j = 0; j < 3; j++) {
        int ls = l0 - 3 + j;
        if (ls >= 0) {
            size_t base = ((size_t)(b * L_DIM + ls)) * D_MODEL + d;
            wk[j] = *(const float2*)&g_kpre[base];
            wq[j] = *(const float2*)&g_qpre[base];
            wv[j] = *(const float2*)&g_vpre[base];
        } else {
            wk[j] = wq[j] = wv[j] = make_float2(0.f, 0.f);
        }
    }
    __syncthreads();

#pragma unroll
    for (int t = 0; t < 4; t++) {
        {
            size_t base = ((size_t)(b * L_DIM + l0 + t)) * D_MODEL + d;
            wk[(t + 3) & 3] = *(const float2*)&g_kpre[base];
            wq[(t + 3) & 3] = *(const float2*)&g_qpre[base];
            wv[(t + 3) & 3] = *(const float2*)&g_vpre[base];
        }
        float ak0 = 0.f, ak1 = 0.f, aq0 = 0.f, aq1 = 0.f, av0 = 0.f, av1 = 0.f;
#pragma unroll
        for (int j = 0; j < 4; j++) {
            const int sl = (t + j) & 3;
            float wk0 = ((const float*)&cwk[0])[j], wk1 = ((const float*)&cwk[1])[j];
            float wq0 = ((const float*)&cwq[0])[j], wq1 = ((const float*)&cwq[1])[j];
            float wv0 = ((const float*)&cwv[0])[j], wv1 = ((const float*)&cwv[1])[j];
            ak0 += wk[sl].x * wk0; ak1 += wk[sl].y * wk1;
            aq0 += wq[sl].x * wq0; aq1 += wq[sl].y * wq1;
            av0 += wv[sl].x * wv0; av1 += wv[sl].y * wv1;
        }
        float sk = ak0 * ak0 + ak1 * ak1;
        float sq = aq0 * aq0 + aq1 * aq1;
#pragma unroll
        for (int o = 16; o > 0; o >>= 1) {
            sk += __shfl_xor_sync(0xffffffffu, sk, o);
            sq += __shfl_xor_sync(0xffffffffu, sq, o);
        }
        const float rkn = 1.f / (sqrtf(sk) + 1e-6f);
        const float rqn = 1.f / (sqrtf(sq) + 1e-6f);
        const float e = eta_s[t][h];

        float kn0 = ak0 * rkn, kn1 = ak1 * rkn;
        float qn0 = aq0 * rqn, qn1 = aq1 * rqn;
        float sv0 = av0 / (1.f + __expf(-av0));
        float sv1 = av1 / (1.f + __expf(-av1));
        size_t obase = (((size_t)(b * N_HEADS + h)) * L_DIM + l0 + t) * D_HEAD + (d & 63);
        *(float2*)&g_kn[obase] = make_float2(kn0, kn1);
        *(float2*)&g_qn[obase] = make_float2(qn0, qn1);
        *(float2*)&g_vs[obase] = make_float2(e * sv0, e * sv1);
        *(float2*)&g_bb[obase] = make_float2(e * kn0, e * kn1);
    }
}

/* ---------------- chunked o2b weighted delta-rule scan (round-13 version) --- */
#define SPLIT_ST(ah_, al_, idx_, val_) do {                                   \
        __half _hh = __float2half_rn(val_);                                   \
        (ah_)[idx_] = _hh;                                                    \
        (al_)[idx_] = __float2half_rn((val_) - __half2float(_hh));            \
    } while (0)

#define DSM_BYTES ((2 * 64 * FS + 3 * 64 * HSX + 512 + 256) * 4 +             \
                   (10 * F16T + 8 * F16H) * 2)

__global__ __launch_bounds__(256) void delta_kernel()
{
    extern __shared__ float smd[];
    float* Ts   = smd;
    float* Qk   = Ts + 64 * FS;
    float* Wt   = Qk + 64 * FS;
    float* Wa   = Wt + 64 * HSX;
    float* Us   = Wa + 64 * HSX;
    float* invD = Us + 64 * HSX;
    float* Mb   = invD + 512;
    __half* Kh   = (__half*)(Mb + 256);
    __half* Kl   = Kh  + F16T;
    __half* Qh   = Kl  + F16T;
    __half* Ql   = Qh  + F16T;
    __half* Bh2  = Ql  + F16T;
    __half* Bl2  = Bh2 + F16T;
    __half* KTh  = Bl2 + F16T;
    __half* KTl  = KTh + F16T;
    __half* Sh   = KTl + F16T;
    __half* Sl   = Sh  + F16T;
    __half* WtTh = Sl  + F16T;
    __half* WtTl = WtTh + F16H;
    __half* WaTh = WtTl + F16H;
    __half* WaTl = WaTh + F16H;
    __half* UTh  = WaTl + F16H;
    __half* UTl  = UTh + F16H;
    __half* UwTh = UTl + F16H;
    __half* UwTl = UwTh + F16H;

    const int tid = threadIdx.x;
    const int lane = tid & 31, w = tid >> 5;
    const int g = lane >> 2, tg = lane & 3;
    const int arow = (lane & 7) + ((lane >> 3) & 1) * 8;
    const int acol = (lane >> 4) * 8;
    const int brow = ((lane >> 4) & 1) * 8 + (lane & 7);
    const int bcol = ((lane >> 3) & 1) * 8;

    const int pair = blockIdx.x >> 1;
    const int half = blockIdx.x & 1;
    const int col0 = half * 32;
    const int b = pair >> 4, h = pair & 15;

    for (int i = tid; i < 64 * HSX; i += 256) { Wt[i] = 0.f; Wa[i] = 0.f; }

    const size_t pbase = (size_t)pair * L_DIM * D_HEAD;
    const uint32_t khB = smem_u32(Kh), klB = smem_u32(Kl);

    for (int chunk = 0; chunk < N_CHUNK; chunk++) {
        __syncthreads();
        const size_t cb = pbase + (size_t)chunk * 64 * D_HEAD;
        for (int i2 = tid; i2 < 4096; i2 += 256) {
            int r = i2 >> 6, c = i2 & 63;
            float kv = g_kn[cb + i2];
            float qv = g_qn[cb + i2];
            float bv = g_bb[cb + i2];
            SPLIT_ST(Kh, Kl, r * HX + c, kv);
            SPLIT_ST(KTh, KTl, c * HX + r, kv);
            SPLIT_ST(Qh, Ql, r * HX + c, qv);
            SPLIT_ST(Bh2, Bl2, r * HX + c, bv);
        }
        for (int i2 = tid; i2 < 2048; i2 += 256) {
            int r = i2 >> 5, c = i2 & 31;
            Us[r * HSX + c] = g_vs[cb + r * 64 + col0 + c];
        }
        for (int i2 = tid; i2 < 2048; i2 += 256) {
            int m = i2 >> 5, n = i2 & 31;
            SPLIT_ST(WtTh, WtTl, n * HX + m, Wt[m * HSX + n]);
            SPLIT_ST(WaTh, WaTl, n * HX + m, Wa[m * HSX + n]);
        }
        __syncthreads();

        const float ts    = (float)(chunk * 64);
        const float tri0  = 0.5f * (1.f + ts) * ts;
        const float denw  = 0.5f * (65.f + ts) * (64.f + ts);
        const float Ssum  = 64.f * ts + 2080.f;
        const float coef1 = (ts / (ts + 64.f)) * ((1.f + ts) / (ts + 65.f));
        const float coef2 = (64.f / (ts + 64.f)) * ((2.f * ts + 65.f) / (ts + 65.f));

        /* PASS 1a: [B;Q] @ K^T -> T (warps 0-3, tril) / QK (warps 4-7) */
        {
            const uint32_t ahB = smem_u32((w < 4) ? Bh2 : Qh);
            const uint32_t alB = smem_u32((w < 4) ? Bl2 : Ql);
            const int r0 = (w & 3) * 16;
            float acc[8][4];
#pragma unroll
            for (int j = 0; j < 8; j++)
#pragma unroll
                for (int e = 0; e < 4; e++) acc[j][e] = 0.f;

#pragma unroll
            for (int ks = 0; ks < 4; ks++) {
                const int kc = ks * 16;
                uint32_t ah[4], al[4], bh[4][4], bl[4][4];
                const uint32_t aoff = ((r0 + arow) * HX + kc + acol) * 2;
                LDSM_X4(ah, ahB + aoff);
                LDSM_X4(al, alB + aoff);
#pragma unroll
                for (int nt = 0; nt < 4; nt++) {
                    const uint32_t boff = ((nt * 16 + brow) * HX + kc + bcol) * 2;
                    LDSM_X4(bh[nt], khB + boff);
                    LDSM_X4(bl[nt], klB + boff);
                }
#pragma unroll
                for (int j = 0; j < 8; j++) {
                    const int grp = j >> 1, p = (j & 1) * 2;
                    MMA_F16B(acc[j], ah, bh[grp][p], bh[grp][p + 1]);
                    MMA_F16B(acc[j], ah, bl[grp][p], bl[grp][p + 1]);
                    MMA_F16B(acc[j], al, bh[grp][p], bh[grp][p + 1]);
                }
            }
            if (w < 4) {
#pragma unroll
                for (int j = 0; j < 8; j++) {
                    const int C = j * 8 + tg * 2;
                    const int R1 = r0 + g, R2 = r0 + g + 8;
                    Ts[R1 * FS + C]     = (R1 > C)     ? acc[j][0] : 0.f;
                    Ts[R1 * FS + C + 1] = (R1 > C + 1) ? acc[j][1] : 0.f;
                    Ts[R2 * FS + C]     = (R2 > C)     ? acc[j][2] : 0.f;
                    Ts[R2 * FS + C + 1] = (R2 > C + 1) ? acc[j][3] : 0.f;
                }
            } else {
#pragma unroll
                for (int j = 0; j < 8; j++) {
                    const int C = j * 8 + tg * 2;
                    const int R1 = r0 + g, R2 = r0 + g + 8;
                    Qk[R1 * FS + C]     = acc[j][0];
                    Qk[R1 * FS + C + 1] = acc[j][1];
                    Qk[R2 * FS + C]     = acc[j][2];
                    Qk[R2 * FS + C + 1] = acc[j][3];
                }
            }
        }

        /* PASS 1b: RHS = V - B @ Wt */
        {
            const uint32_t b2h = smem_u32(Bh2), b2l = smem_u32(Bl2);
            const uint32_t wth = smem_u32(WtTh), wtl = smem_u32(WtTl);
            const int bm0 = (w & 3) * 16;
            const int bn0 = (w >> 2) * 16;
            float accB[2][4];
#pragma unroll
            for (int nt = 0; nt < 2; nt++)
#pragma unroll
                for (int e = 0; e < 4; e++) accB[nt][e] = 0.f;
#pragma unroll
            for (int ks = 0; ks < 4; ks++) {
                const int kc = ks * 16;
                uint32_t ah[4], al[4], bh[4], bl[4];
                const uint32_t aoff = ((bm0 + arow) * HX + kc + acol) * 2;
                LDSM_X4(ah, b2h + aoff);
                LDSM_X4(al, b2l + aoff);
                const uint32_t boff = ((bn0 + brow) * HX + kc + bcol) * 2;
                LDSM_X4(bh, wth + boff);
                LDSM_X4(bl, wtl + boff);
#pragma unroll
                for (int nt = 0; nt < 2; nt++) {
                    const int p = nt * 2;
                    MMA_F16B(accB[nt], ah, bh[p], bh[p + 1]);
                    MMA_F16B(accB[nt], ah, bl[p], bl[p + 1]);
                    MMA_F16B(accB[nt], al, bh[p], bh[p + 1]);
                }
            }
#pragma unroll
            for (int nt = 0; nt < 2; nt++) {
                const int col = bn0 + nt * 8 + tg * 2;
                const int R1 = bm0 + g, R2 = bm0 + g + 8;
                Us[R1 * HSX + col]     -= accB[nt][0];
                Us[R1 * HSX + col + 1] -= accB[nt][1];
                Us[R2 * HSX + col]     -= accB[nt][2];
                Us[R2 * HSX + col + 1] -= accB[nt][3];
            }
        }
        __syncthreads();

        /* C0: invert the 8 unit-lower 8x8 diagonal blocks */
        if (tid < 64) {
            const int blk = tid >> 3, c = tid & 7;
            const int r0 = blk * 8;
            float xcol[8];
#pragma unroll
            for (int r = 0; r < 8; r++) {
                float s = (r == c) ? 1.f : 0.f;
                for (int k2 = c; k2 < r; k2++)
                    s -= Ts[(r0 + r) * FS + r0 + k2] * xcol[k2];
                xcol[r] = s;
            }
#pragma unroll
            for (int r = 0; r < 8; r++) invD[(r0 + r) * 8 + c] = xcol[r];
        }
        __syncthreads();

        /* C: blocked forward substitution (I+T) U = RHS */
        {
            const int cc = tid & 31, rr = tid >> 5;
            for (int ib = 0; ib < 8; ib++) {
                const int r0 = ib * 8;
                float s = 0.f;
                for (int j = 0; j < r0; j++)
                    s += Ts[(r0 + rr) * FS + j] * Us[j * HSX + cc];
                float rhs = Us[(r0 + rr) * HSX + cc] - s;
                Mb[rr * 32 + cc] = rhs;
                __syncthreads();
                s = rhs;
                for (int k2 = 0; k2 < rr; k2++)
                    s += invD[(r0 + rr) * 8 + k2] * Mb[k2 * 32 + cc];
                Us[(r0 + rr) * HSX + cc] = s;
                __syncthreads();
            }
        }

        /* conversions: S = weights o QK; U^T and (U*w)^T in fp16 hi/lo */
        for (int i2 = tid; i2 < 4096; i2 += 256) {
            int r = i2 >> 6, c = i2 & 63;
            float rr2 = (float)r;
            float cs_r = (rr2 + 1.f) * ts + 0.5f * (rr2 + 1.f) * (rr2 + 2.f);
            float rdiv = 1.f / (tri0 + cs_r);
            float kf = (float)c;
            float csk_m = kf * ts + 0.5f * kf * (kf + 1.f);
            float num = cs_r - csk_m;
            float sfac = (num >= 0.f) ? num * rdiv : 0.f;
            float sv = sfac * Qk[r * FS + c];
            SPLIT_ST(Sh, Sl, r * HX + c, sv);
        }
        for (int i2 = tid; i2 < 2048; i2 += 256) {
            int c = i2 >> 6, r = i2 & 63;
            float u = Us[r * HSX + c];
            float rr2 = (float)r;
            float idxr = ts + rr2 + 1.f;
            float csrr = (rr2 + 1.f) * ts + 0.5f * (rr2 + 1.f) * (rr2 + 2.f);
            float wr = (idxr + Ssum - csrr) / denw;
            SPLIT_ST(UTh, UTl, c * HX + r, u);
            SPLIT_ST(UwTh, UwTl, c * HX + r, u * wr);
        }
        __syncthreads();

        /* PASS 2: warps 0-3 -> O (D + F); warps 4-7 -> H (W updates) */
        if (w < 4) {
            const int r0 = w * 16;
            const uint32_t qhB = smem_u32(Qh), qlB = smem_u32(Ql);
            const uint32_t shB = smem_u32(Sh), slB = smem_u32(Sl);
            const uint32_t wah = smem_u32(WaTh), wal = smem_u32(WaTl);
            const uint32_t wth = smem_u32(WtTh), wtl = smem_u32(WtTl);
            const uint32_t uth = smem_u32(UTh), utl = smem_u32(UTl);
            float aA[4][4], aT[4][4], aF[4][4];
#pragma unroll
            for (int nt = 0; nt < 4; nt++)
#pragma unroll
                for (int e = 0; e < 4; e++) { aA[nt][e] = 0.f; aT[nt][e] = 0.f; aF[nt][e] = 0.f; }

#pragma unroll
            for (int ks = 0; ks < 4; ks++) {
                const int kc = ks * 16;
                const uint32_t aoff = ((r0 + arow) * HX + kc + acol) * 2;
                uint32_t qh[4], ql[4], sh[4], sl[4];
                LDSM_X4(qh, qhB + aoff);
                LDSM_X4(ql, qlB + aoff);
                LDSM_X4(sh, shB + aoff);
                LDSM_X4(sl, slB + aoff);
                uint32_t bwa[2][4], bwa2[2][4], bwt[2][4], bwt2[2][4], bu[2][4], bu2[2][4];
#pragma unroll
                for (int a2 = 0; a2 < 2; a2++) {
                    const uint32_t boff = ((a2 * 16 + brow) * HX + kc + bcol) * 2;
                    LDSM_X4(bwa[a2], wah + boff);
                    LDSM_X4(bwa2[a2], wal + boff);
                    LDSM_X4(bwt[a2], wth + boff);
                    LDSM_X4(bwt2[a2], wtl + boff);
                    LDSM_X4(bu[a2], uth + boff);
                    LDSM_X4(bu2[a2], utl + boff);
                }
#pragma unroll
                for (int nt = 0; nt < 4; nt++) {
                    const int grp = nt >> 1, p = (nt & 1) * 2;
                    MMA_F16B(aA[nt], qh, bwa[grp][p], bwa[grp][p + 1]);
                    MMA_F16B(aA[nt], qh, bwa2[grp][p], bwa2[grp][p + 1]);
                    MMA_F16B(aA[nt], ql, bwa[grp][p], bwa[grp][p + 1]);
                    MMA_F16B(aT[nt], qh, bwt[grp][p], bwt[grp][p + 1]);
                    MMA_F16B(aT[nt], qh, bwt2[grp][p], bwt2[grp][p + 1]);
                    MMA_F16B(aT[nt], ql, bwt[grp][p], bwt[grp][p + 1]);
                    MMA_F16B(aF[nt], sh, bu[grp][p], bu[grp][p + 1]);
                    MMA_F16B(aF[nt], sh, bu2[grp][p], bu2[grp][p + 1]);
                    MMA_F16B(aF[nt], sl, bu[grp][p], bu[grp][p + 1]);
                }
            }
            const int r1 = r0 + g, r2 = r1 + 8;
            float f1 = (float)r1, f2 = (float)r2;
            float cs1 = (f1 + 1.f) * ts + 0.5f * (f1 + 1.f) * (f1 + 2.f);
            float cs2 = (f2 + 1.f) * ts + 0.5f * (f2 + 1.f) * (f2 + 2.f);
            float ar1 = tri0 / (tri0 + cs1);
            float ar2 = tri0 / (tri0 + cs2);
#pragma unroll
            for (int nt = 0; nt < 4; nt++) {
                const int cg = h * 64 + col0 + nt * 8 + tg * 2;
                int l1 = chunk * 64 + r1, l2 = chunk * 64 + r2;
                float2 v1 = make_float2(
                    ar1 * aA[nt][0] + (1.f - ar1) * aT[nt][0] + aF[nt][0],
                    ar1 * aA[nt][1] + (1.f - ar1) * aT[nt][1] + aF[nt][1]);
                float2 v2 = make_float2(
                    ar2 * aA[nt][2] + (1.f - ar2) * aT[nt][2] + aF[nt][2],
                    ar2 * aA[nt][3] + (1.f - ar2) * aT[nt][3] + aF[nt][3]);
                *(float2*)&g_o[((size_t)(b * L_DIM + l1)) * D_MODEL + cg] = v1;
                *(float2*)&g_o[((size_t)(b * L_DIM + l2)) * D_MODEL + cg] = v2;
            }
        } else {
            const int m0 = (w - 4) * 16;
            const uint32_t kth = smem_u32(KTh), ktl = smem_u32(KTl);
            const uint32_t uth = smem_u32(UTh), utl = smem_u32(UTl);
            const uint32_t uwh = smem_u32(UwTh), uwl = smem_u32(UwTl);
            float p1a[4][4], p2a[4][4];
#pragma unroll
            for (int nt = 0; nt < 4; nt++)
#pragma unroll
                for (int e = 0; e < 4; e++) { p1a[nt][e] = 0.f; p2a[nt][e] = 0.f; }

#pragma unroll
            for (int ks = 0; ks < 4; ks++) {
                const int kc = ks * 16;
                const uint32_t aoff = ((m0 + arow) * HX + kc + acol) * 2;
                uint32_t kh2[4], kl2[4];
                LDSM_X4(kh2, kth + aoff);
                LDSM_X4(kl2, ktl + aoff);
                uint32_t bu[2][4], bu2[2][4], bw[2][4], bw2[2][4];
#pragma unroll
                for (int a2 = 0; a2 < 2; a2++) {
                    const uint32_t boff = ((a2 * 16 + brow) * HX + kc + bcol) * 2;
                    LDSM_X4(bu[a2], uth + boff);
                    LDSM_X4(bu2[a2], utl + boff);
                    LDSM_X4(bw[a2], uwh + boff);
                    LDSM_X4(bw2[a2], uwl + boff);
                }
#pragma unroll
                for (int nt = 0; nt < 4; nt++) {
                    const int grp = nt >> 1, p = (nt & 1) * 2;
                    MMA_F16B(p1a[nt], kh2, bu[grp][p], bu[grp][p + 1]);
                    MMA_F16B(p1a[nt], kh2, bu2[grp][p], bu2[grp][p + 1]);
                    MMA_F16B(p1a[nt], kl2, bu[grp][p], bu[grp][p + 1]);
                    MMA_F16B(p2a[nt], kh2, bw[grp][p], bw[grp][p + 1]);
                    MMA_F16B(p2a[nt], kh2, bw2[grp][p], bw2[grp][p + 1]);
                    MMA_F16B(p2a[nt], kl2, bw[grp][p], bw[grp][p + 1]);
                }
            }
            const int m1 = m0 + g, m2 = m1 + 8;
#pragma unroll
            for (int nt = 0; nt < 4; nt++) {
                const int n = nt * 8 + tg * 2;
#pragma unroll
                for (int cc2 = 0; cc2 < 2; cc2++) {
                    int i1 = m1 * HSX + n + cc2;
                    float wo = Wt[i1];
                    Wa[i1] = coef1 * Wa[i1] + coef2 * wo + p2a[nt][cc2];
                    Wt[i1] = wo + p1a[nt][cc2];
                    int i2x = m2 * HSX + n + cc2;
                    wo = Wt[i2x];
                    Wa[i2x] = coef1 * Wa[i2x] + coef2 * wo + p2a[nt][2 + cc2];
                    Wt[i2x] = wo + p1a[nt][2 + cc2];
                }
            }
        }
    }
}

/* -------- RMS norm over head dim + fp16 (hi only) for final 2-pass GEMM ----- */
__global__ __launch_bounds__(256) void rms_split(const float* __restrict__ rms_w)
{
    const int bl = blockIdx.x, tid = threadIdx.x;
    float4 v = ((const float4*)g_o)[(size_t)bl * 256 + tid];
    float ss = v.x * v.x + v.y * v.y + v.z * v.z + v.w * v.w;
#pragma unroll
    for (int o = 8; o > 0; o >>= 1) ss += __shfl_xor_sync(0xffffffffu, ss, o);
    float scale = rsqrtf(ss * (1.f / 64.f) + 1e-6f);
    float4 rw = ((const float4*)rms_w)[tid & 15];
    float a0 = v.x * scale * rw.x, a1 = v.y * scale * rw.y;
    float a2 = v.z * scale * rw.z, a3 = v.w * scale * rw.w;
    __half2 h01 = __floats2half2_rn(a0, a1);
    __half2 h23 = __floats2half2_rn(a2, a3);
    ((uint2*)g_oh)[(size_t)bl * 256 + tid] = make_uint2(*(uint32_t*)&h01, *(uint32_t*)&h23);
}

/* ------------------------------- launcher ----------------------------------*/
extern "C" void kernel_launch(void* const* d_in, const int* in_sizes, int n_in,
                              void* d_out, int out_size)
{
    (void)in_sizes; (void)n_in; (void)out_size;
    const float* x     = (const float*)d_in[0];
    const float* Wk    = (const float*)d_in[1];
    const float* bk    = (const float*)d_in[2];
    const float* Wq    = (const float*)d_in[3];
    const float* bq    = (const float*)d_in[4];
    const float* Wv    = (const float*)d_in[5];
    const float* bv    = (const float*)d_in[6];
    const float* Wbeta = (const float*)d_in[7];
    const float* bbeta = (const float*)d_in[8];
    const float* ck    = (const float*)d_in[9];
    const float* cq    = (const float*)d_in[10];
    const float* cv    = (const float*)d_in[11];
    const float* rms_w = (const float*)d_in[12];
    const float* Wout  = (const float*)d_in[13];
    const float* bout  = (const float*)d_in[14];
    float* out = (float*)d_out;

    float *kpre, *qpre, *vpre;
    __half *xh, *oh, *wsh, *wsl;
    cudaGetSymbolAddress((void**)&kpre, g_kpre);
    cudaGetSymbolAddress((void**)&qpre, g_qpre);
    cudaGetSymbolAddress((void**)&vpre, g_vpre);
    cudaGetSymbolAddress((void**)&xh, g_xh);
    cudaGetSymbolAddress((void**)&oh, g_oh);
    cudaGetSymbolAddress((void**)&wsh, g_wsh);
    cudaGetSymbolAddress((void**)&wsl, g_wsl);

    split_hi<<<(ML * D_MODEL / 4 + 255) / 256, 256>>>(
        (const float4*)x, (uint2*)xh, ML * D_MODEL / 4);
    split_w4<<<(4 * DD / 4) / 256, 256>>>(
        (const float4*)Wk, (const float4*)Wq, (const float4*)Wv,
        (const float4*)Wout, (uint2*)wsh, (uint2*)wsl);

    cudaFuncSetAttribute(gemm_qkv2, cudaFuncAttributeMaxDynamicSharedMemorySize,
                         QSM_BYTES);
    cudaFuncSetAttribute(gemm_h2b, cudaFuncAttributeMaxDynamicSharedMemorySize,
                         QSM_BYTES);

    gemm_qkv2<<<dim3(24, 64), 256, QSM_BYTES>>>(
        xh, wsh, wsl, bk, bq, bv, kpre, qpre, vpre, ML, D_MODEL);

    prep4<<<B_DIM * (L_DIM / 4), 512>>>(x, Wbeta, bbeta, ck, cq, cv);

    cudaFuncSetAttribute(delta_kernel, cudaFuncAttributeMaxDynamicSharedMemorySize,
                         DSM_BYTES);
    delta_kernel<<<2 * N_PAIR, 256, DSM_BYTES>>>();

    rms_split<<<ML, 256>>>(rms_w);

    gemm_h2b<<<dim3(8, 64), 256, QSM_BYTES>>>(
        oh, wsh + 3 * DD, wsl + 3 * DD, bout, out, ML, D_MODEL);
}

// round 17
// speedup vs baseline: 1.1593x; 1.1285x over previous
#include <cuda_runtime.h>
#include <cuda_fp16.h>
#include <math.h>
#include <stdint.h>

#define B_DIM   4
#define L_DIM   2048
#define D_MODEL 1024
#define N_HEADS 16
#define D_HEAD  64
#define ML      (B_DIM * L_DIM)
#define N_PAIR  (B_DIM * N_HEADS)
#define N_CHUNK (L_DIM / 64)
#define DD      (D_MODEL * D_MODEL)
#define FS      65                       /* full fp32 smem stride */
#define HSX     33                       /* half-width fp32 smem stride */
#define HX      72                       /* fp16 tile stride (halves) */
#define F16T    (64 * HX)
#define F16H    (32 * HX)

/* ---------------- scratch (device globals; no runtime alloc) ---------------- */
__device__ float  g_kpre[ML * D_MODEL];
__device__ float  g_qpre[ML * D_MODEL];
__device__ float  g_vpre[ML * D_MODEL];
__device__ float  g_kn  [ML * D_MODEL];
__device__ float  g_qn  [ML * D_MODEL];
__device__ float  g_vs  [ML * D_MODEL];
__device__ float  g_bb  [ML * D_MODEL];
__device__ float  g_o   [ML * D_MODEL];
__device__ __half g_xh  [ML * D_MODEL];
__device__ __half g_oh  [ML * D_MODEL];
__device__ __half g_wsh [4 * DD];
__device__ __half g_wsl [DD];            /* Wout lo only (final GEMM 2-pass) */

/* ---------------- fp32 -> fp16 splits, vectorized --------------------------- */
__device__ __forceinline__ void split4(float4 v, uint2& hi, uint2& lo) {
    __half2 h01 = __floats2half2_rn(v.x, v.y);
    __half2 h23 = __floats2half2_rn(v.z, v.w);
    __half2 l01 = __floats2half2_rn(v.x - __low2float(h01), v.y - __high2float(h01));
    __half2 l23 = __floats2half2_rn(v.z - __low2float(h23), v.w - __high2float(h23));
    hi = make_uint2(*(uint32_t*)&h01, *(uint32_t*)&h23);
    lo = make_uint2(*(uint32_t*)&l01, *(uint32_t*)&l23);
}

__global__ __launch_bounds__(256) void split_hi(
    const float4* __restrict__ src, uint2* __restrict__ hi, int n4)
{
    int i = blockIdx.x * blockDim.x + threadIdx.x;
    if (i >= n4) return;
    float4 v = src[i];
    __half2 h01 = __floats2half2_rn(v.x, v.y);
    __half2 h23 = __floats2half2_rn(v.z, v.w);
    hi[i] = make_uint2(*(uint32_t*)&h01, *(uint32_t*)&h23);
}

/* all 4 weight matrices -> hi; Wout additionally -> lo */
__global__ __launch_bounds__(256) void split_w4(
    const float4* __restrict__ w0, const float4* __restrict__ w1,
    const float4* __restrict__ w2, const float4* __restrict__ w3,
    uint2* __restrict__ hi, uint2* __restrict__ lo)
{
    int i = blockIdx.x * blockDim.x + threadIdx.x;
    int seg = i >> 18;
    int off = i & ((DD / 4) - 1);
    const float4* src = (seg == 0) ? w0 : (seg == 1) ? w1 : (seg == 2) ? w2 : w3;
    uint2 h, l;
    split4(src[off], h, l);
    hi[i] = h;
    if (seg == 3) lo[off] = l;
}

/* =================== tensor-core GEMM machinery (FP16) ====================== */
#define HS      40

__device__ __forceinline__ uint32_t smem_u32(const void* p) {
    uint32_t a;
    asm("{ .reg .u64 t; cvta.to.shared.u64 t, %1; cvt.u32.u64 %0, t; }"
        : "=r"(a) : "l"(p));
    return a;
}

#define LDSM_X4(r, a)                                                         \
    asm volatile("ldmatrix.sync.aligned.m8n8.x4.shared.b16 "                  \
                 "{%0,%1,%2,%3}, [%4];"                                       \
                 : "=r"((r)[0]), "=r"((r)[1]), "=r"((r)[2]), "=r"((r)[3])     \
                 : "r"(a))

#define MMA_F16B(d, a, b0, b1)                                                \
    asm volatile(                                                             \
        "mma.sync.aligned.m16n8k16.row.col.f32.f16.f16.f32 "                  \
        "{%0,%1,%2,%3}, {%4,%5,%6,%7}, {%8,%9}, {%0,%1,%2,%3};"               \
        : "+f"(d[0]), "+f"(d[1]), "+f"(d[2]), "+f"(d[3])                      \
        : "r"(a[0]), "r"(a[1]), "r"(a[2]), "r"(a[3]), "r"(b0), "r"(b1))

#define CP_ASYNC16(sa, gp)                                                    \
    asm volatile("cp.async.cg.shared.global [%0], [%1], 16;"                  \
                 :: "r"(sa), "l"(gp))

/* ---------- QKV: PURE fp16 single-pass, CTA 128x128, 3 stages, 1 sync/tile -- */
#define P1_AH   0
#define P1_BH   10240
#define P1STG   20480
#define P1_BYTES (3 * P1STG)

__global__ __launch_bounds__(256, 2) void gemm_qkv1(
    const __half* __restrict__ Ahg, const __half* __restrict__ Bhg,
    const float* __restrict__ bk, const float* __restrict__ bq,
    const float* __restrict__ bv,
    float* __restrict__ Yk, float* __restrict__ Yq, float* __restrict__ Yv,
    int M, int K)
{
    extern __shared__ char smg[];
    const uint32_t sbase = smem_u32(smg);

    const int tid = threadIdx.x;
    const int bm = blockIdx.y * 128;
    const int bnG = blockIdx.x * 128;
    const int seg = bnG >> 10;
    const int bnL = bnG & 1023;
    const float* bias = (seg == 0) ? bk : (seg == 1) ? bq : bv;
    float* Y = (seg == 0) ? Yk : (seg == 1) ? Yq : Yv;

    const int lane = tid & 31, w = tid >> 5;
    const int wm = (w >> 2) * 64, wn = (w & 3) * 32;
    const int g = lane >> 2, tg = lane & 3;
    const int arow = (lane & 7) + ((lane >> 3) & 1) * 8;
    const int acol = (lane >> 4) * 8;
    const int brow = ((lane >> 4) & 1) * 8 + (lane & 7);
    const int bcol = ((lane >> 3) & 1) * 8;
    const int r4 = tid >> 2, c4 = tid & 3;
    const uint32_t so = r4 * 80 + c4 * 16;

    float acc[4][4][4];
#pragma unroll
    for (int mt = 0; mt < 4; mt++)
#pragma unroll
        for (int nt = 0; nt < 4; nt++)
#pragma unroll
            for (int e = 0; e < 4; e++) acc[mt][nt][e] = 0.f;

    const int n_tiles = K >> 5;

#define P1LOAD(t) do {                                                        \
        const uint32_t _sb = sbase + ((t) % 3) * P1STG;                       \
        const int _kb = (t) << 5;                                             \
        const size_t _ga0 = (size_t)(bm + r4) * K + _kb + c4 * 8;             \
        const size_t _ga1 = (size_t)(bm + 64 + r4) * K + _kb + c4 * 8;        \
        const size_t _gb0 = (size_t)(bnG + r4) * K + _kb + c4 * 8;            \
        const size_t _gb1 = (size_t)(bnG + 64 + r4) * K + _kb + c4 * 8;       \
        CP_ASYNC16(_sb + P1_AH + so,        Ahg + _ga0);                      \
        CP_ASYNC16(_sb + P1_AH + so + 5120, Ahg + _ga1);                      \
        CP_ASYNC16(_sb + P1_BH + so,        Bhg + _gb0);                      \
        CP_ASYNC16(_sb + P1_BH + so + 5120, Bhg + _gb1);                      \
        asm volatile("cp.async.commit_group;");                               \
    } while (0)

    P1LOAD(0);
    P1LOAD(1);
    for (int t = 0; t < n_tiles; t++) {
        if (t + 1 < n_tiles) asm volatile("cp.async.wait_group 1;");
        else                 asm volatile("cp.async.wait_group 0;");
        __syncthreads();
        if (t + 2 < n_tiles) P1LOAD(t + 2);
        const uint32_t sb = sbase + (t % 3) * P1STG;
#pragma unroll
        for (int kk = 0; kk < 2; kk++) {
            const int kc = kk * 16;
            uint32_t ah[4][4], bh[2][4];
#pragma unroll
            for (int mt = 0; mt < 4; mt++) {
                uint32_t ad = sb + P1_AH +
                              ((wm + mt * 16 + arow) * HS + kc + acol) * 2;
                LDSM_X4(ah[mt], ad);
            }
#pragma unroll
            for (int a2 = 0; a2 < 2; a2++) {
                uint32_t bd = sb + P1_BH +
                              ((wn + a2 * 16 + brow) * HS + kc + bcol) * 2;
                LDSM_X4(bh[a2], bd);
            }
#pragma unroll
            for (int mt = 0; mt < 4; mt++)
#pragma unroll
                for (int nt = 0; nt < 4; nt++) {
                    const int hi2 = nt >> 1, p = (nt & 1) * 2;
                    MMA_F16B(acc[mt][nt], ah[mt], bh[hi2][p], bh[hi2][p + 1]);
                }
        }
    }
#undef P1LOAD

#pragma unroll
    for (int mt = 0; mt < 4; mt++) {
        const int row = bm + wm + mt * 16 + g;
#pragma unroll
        for (int nt = 0; nt < 4; nt++) {
            const int col = bnL + wn + nt * 8 + tg * 2;
            const float b0 = bias[col], b1 = bias[col + 1];
            float2 v0 = make_float2(acc[mt][nt][0] + b0, acc[mt][nt][1] + b1);
            float2 v1 = make_float2(acc[mt][nt][2] + b0, acc[mt][nt][3] + b1);
            *(float2*)(Y + (size_t)row * D_MODEL + col) = v0;
            *(float2*)(Y + (size_t)(row + 8) * D_MODEL + col) = v1;
        }
    }
}

/* ---------- final GEMM: 2-pass (A hi; B hi+lo), CTA 128x128, 1 sync/tile ---- */
#define QS_AH   0
#define QS_BH   10240
#define QS_BL   20480
#define QSTG    30720
#define QSM_BYTES (3 * QSTG)

__global__ __launch_bounds__(256, 2) void gemm_h2b(
    const __half* __restrict__ Ahg,
    const __half* __restrict__ Bhg, const __half* __restrict__ Blg,
    const float* __restrict__ bias, float* __restrict__ Y,
    int M, int K)
{
    extern __shared__ char smg[];
    const uint32_t sbase = smem_u32(smg);

    const int tid = threadIdx.x;
    const int bm = blockIdx.y * 128;
    const int bnG = blockIdx.x * 128;
    const int bnL = bnG;

    const int lane = tid & 31, w = tid >> 5;
    const int wm = (w >> 2) * 64, wn = (w & 3) * 32;
    const int g = lane >> 2, tg = lane & 3;
    const int arow = (lane & 7) + ((lane >> 3) & 1) * 8;
    const int acol = (lane >> 4) * 8;
    const int brow = ((lane >> 4) & 1) * 8 + (lane & 7);
    const int bcol = ((lane >> 3) & 1) * 8;
    const int r4 = tid >> 2, c4 = tid & 3;
    const uint32_t so = r4 * 80 + c4 * 16;

    float acc[4][4][4];
#pragma unroll
    for (int mt = 0; mt < 4; mt++)
#pragma unroll
        for (int nt = 0; nt < 4; nt++)
#pragma unroll
            for (int e = 0; e < 4; e++) acc[mt][nt][e] = 0.f;

    const int n_tiles = K >> 5;

#define QLOAD(t) do {                                                         \
        const uint32_t _sb = sbase + ((t) % 3) * QSTG;                        \
        const int _kb = (t) << 5;                                             \
        const size_t _ga0 = (size_t)(bm + r4) * K + _kb + c4 * 8;             \
        const size_t _ga1 = (size_t)(bm + 64 + r4) * K + _kb + c4 * 8;        \
        const size_t _gb0 = (size_t)(bnG + r4) * K + _kb + c4 * 8;            \
        const size_t _gb1 = (size_t)(bnG + 64 + r4) * K + _kb + c4 * 8;       \
        CP_ASYNC16(_sb + QS_AH + so,        Ahg + _ga0);                      \
        CP_ASYNC16(_sb + QS_AH + so + 5120, Ahg + _ga1);                      \
        CP_ASYNC16(_sb + QS_BH + so,        Bhg + _gb0);                      \
        CP_ASYNC16(_sb + QS_BH + so + 5120, Bhg + _gb1);                      \
        CP_ASYNC16(_sb + QS_BL + so,        Blg + _gb0);                      \
        CP_ASYNC16(_sb + QS_BL + so + 5120, Blg + _gb1);                      \
        asm volatile("cp.async.commit_group;");                               \
    } while (0)

    QLOAD(0);
    QLOAD(1);
    for (int t = 0; t < n_tiles; t++) {
        if (t + 1 < n_tiles) asm volatile("cp.async.wait_group 1;");
        else                 asm volatile("cp.async.wait_group 0;");
        __syncthreads();
        if (t + 2 < n_tiles) QLOAD(t + 2);
        const uint32_t sb = sbase + (t % 3) * QSTG;
#pragma unroll
        for (int kk = 0; kk < 2; kk++) {
            const int kc = kk * 16;
            uint32_t ah[4][4], bh[2][4], bl[2][4];
#pragma unroll
            for (int mt = 0; mt < 4; mt++) {
                uint32_t ad = sb + QS_AH +
                              ((wm + mt * 16 + arow) * HS + kc + acol) * 2;
                LDSM_X4(ah[mt], ad);
            }
#pragma unroll
            for (int a2 = 0; a2 < 2; a2++) {
                uint32_t bd = sb + QS_BH +
                              ((wn + a2 * 16 + brow) * HS + kc + bcol) * 2;
                LDSM_X4(bh[a2], bd);
                LDSM_X4(bl[a2], bd + (QS_BL - QS_BH));
            }
#pragma unroll
            for (int mt = 0; mt < 4; mt++)
#pragma unroll
                for (int nt = 0; nt < 4; nt++) {
                    const int hi2 = nt >> 1, p = (nt & 1) * 2;
                    MMA_F16B(acc[mt][nt], ah[mt], bh[hi2][p], bh[hi2][p + 1]);
                    MMA_F16B(acc[mt][nt], ah[mt], bl[hi2][p], bl[hi2][p + 1]);
                }
        }
    }
#undef QLOAD

#pragma unroll
    for (int mt = 0; mt < 4; mt++) {
        const int row = bm + wm + mt * 16 + g;
#pragma unroll
        for (int nt = 0; nt < 4; nt++) {
            const int col = bnL + wn + nt * 8 + tg * 2;
            const float b0 = bias[col], b1 = bias[col + 1];
            float2 v0 = make_float2(acc[mt][nt][0] + b0, acc[mt][nt][1] + b1);
            float2 v1 = make_float2(acc[mt][nt][2] + b0, acc[mt][nt][3] + b1);
            *(float2*)(Y + (size_t)row * D_MODEL + col) = v0;
            *(float2*)(Y + (size_t)(row + 8) * D_MODEL + col) = v1;
        }
    }
}

/* -------- prep4: 4 tokens/CTA, 512 threads, 2 channels/thread --------------- */
__global__ __launch_bounds__(512, 2) void prep4(
    const float* __restrict__ x,
    const float* __restrict__ Wbeta, const float* __restrict__ bbeta,
    const float* __restrict__ ck, const float* __restrict__ cq,
    const float* __restrict__ cv)
{
    __shared__ float xs[4 * D_MODEL];
    __shared__ float eta_s[4][N_HEADS];

    const int bid = blockIdx.x;
    const int b = bid >> 9;
    const int l0 = (bid & 511) * 4;
    const int tid = threadIdx.x;
    const int d = tid * 2;
    const int h = tid >> 5;
    const int lane = tid & 31;
    const int w = tid >> 5;

#pragma unroll
    for (int i = 0; i < 2; i++) {
        int idx = i * 512 + tid;
        int t = idx >> 8, c = idx & 255;
        ((float4*)xs)[t * 256 + c] =
            *(const float4*)(x + ((size_t)(b * L_DIM + l0 + t)) * D_MODEL + c * 4);
    }
    __syncthreads();

    {
        const int t = w >> 2;
        const int hb0 = (w & 3) * 4;
        const float* xr = xs + t * D_MODEL;
#pragma unroll
        for (int hh = 0; hh < 4; hh++) {
            int hb = hb0 + hh;
            float s = 0.f;
            const float* wb = Wbeta + hb * D_MODEL;
            for (int k = lane * 4; k < D_MODEL; k += 128) {
                float4 xv = *(const float4*)(xr + k);
                float4 wv = *(const float4*)(wb + k);
                s += xv.x * wv.x + xv.y * wv.y + xv.z * wv.z + xv.w * wv.w;
            }
#pragma unroll
            for (int o = 16; o > 0; o >>= 1) s += __shfl_down_sync(0xffffffffu, s, o);
            if (lane == 0) eta_s[t][hb] = 1.f / (1.f + __expf(-(s + bbeta[hb])));
        }
    }

    float4 cwk[2], cwq[2], cwv[2];
#pragma unroll
    for (int c = 0; c < 2; c++) {
        cwk[c] = ((const float4*)ck)[d + c];
        cwq[c] = ((const float4*)cq)[d + c];
        cwv[c] = ((const float4*)cv)[d + c];
    }

    float2 wk[4], wq[4], wv[4];
#pragma unroll
    for (int j = 0; j < 3; j++) {
        int ls = l0 - 3 + j;
        if (ls >= 0) {
            size_t base = ((size_t)(b * L_DIM + ls)) * D_MODEL + d;
            wk[j] = *(const float2*)&g_kpre[base];
            wq[j] = *(const float2*)&g_qpre[base];
            wv[j] = *(const float2*)&g_vpre[base];
        } else {
            wk[j] = wq[j] = wv[j] = make_float2(0.f, 0.f);
        }
    }
    __syncthreads();

#pragma unroll
    for (int t = 0; t < 4; t++) {
        {
            size_t base = ((size_t)(b * L_DIM + l0 + t)) * D_MODEL + d;
            wk[(t + 3) & 3] = *(const float2*)&g_kpre[base];
            wq[(t + 3) & 3] = *(const float2*)&g_qpre[base];
            wv[(t + 3) & 3] = *(const float2*)&g_vpre[base];
        }
        float ak0 = 0.f, ak1 = 0.f, aq0 = 0.f, aq1 = 0.f, av0 = 0.f, av1 = 0.f;
#pragma unroll
        for (int j = 0; j < 4; j++) {
            const int sl = (t + j) & 3;
            float wk0 = ((const float*)&cwk[0])[j], wk1 = ((const float*)&cwk[1])[j];
            float wq0 = ((const float*)&cwq[0])[j], wq1 = ((const float*)&cwq[1])[j];
            float wv0 = ((const float*)&cwv[0])[j], wv1 = ((const float*)&cwv[1])[j];
            ak0 += wk[sl].x * wk0; ak1 += wk[sl].y * wk1;
            aq0 += wq[sl].x * wq0; aq1 += wq[sl].y * wq1;
            av0 += wv[sl].x * wv0; av1 += wv[sl].y * wv1;
        }
        float sk = ak0 * ak0 + ak1 * ak1;
        float sq = aq0 * aq0 + aq1 * aq1;
#pragma unroll
        for (int o = 16; o > 0; o >>= 1) {
            sk += __shfl_xor_sync(0xffffffffu, sk, o);
            sq += __shfl_xor_sync(0xffffffffu, sq, o);
        }
        const float rkn = 1.f / (sqrtf(sk) + 1e-6f);
        const float rqn = 1.f / (sqrtf(sq) + 1e-6f);
        const float e = eta_s[t][h];

        float kn0 = ak0 * rkn, kn1 = ak1 * rkn;
        float qn0 = aq0 * rqn, qn1 = aq1 * rqn;
        float sv0 = av0 / (1.f + __expf(-av0));
        float sv1 = av1 / (1.f + __expf(-av1));
        size_t obase = (((size_t)(b * N_HEADS + h)) * L_DIM + l0 + t) * D_HEAD + (d & 63);
        *(float2*)&g_kn[obase] = make_float2(kn0, kn1);
        *(float2*)&g_qn[obase] = make_float2(qn0, qn1);
        *(float2*)&g_vs[obase] = make_float2(e * sv0, e * sv1);
        *(float2*)&g_bb[obase] = make_float2(e * kn0, e * kn1);
    }
}

/* ---------------- chunked o2b weighted delta-rule scan (round-13 version) --- */
#define SPLIT_ST(ah_, al_, idx_, val_) do {                                   \
        __half _hh = __float2half_rn(val_);                                   \
        (ah_)[idx_] = _hh;                                                    \
        (al_)[idx_] = __float2half_rn((val_) - __half2float(_hh));            \
    } while (0)

#define DSM_BYTES ((2 * 64 * FS + 3 * 64 * HSX + 512 + 256) * 4 +             \
                   (10 * F16T + 8 * F16H) * 2)

__global__ __launch_bounds__(256) void delta_kernel()
{
    extern __shared__ float smd[];
    float* Ts   = smd;
    float* Qk   = Ts + 64 * FS;
    float* Wt   = Qk + 64 * FS;
    float* Wa   = Wt + 64 * HSX;
    float* Us   = Wa + 64 * HSX;
    float* invD = Us + 64 * HSX;
    float* Mb   = invD + 512;
    __half* Kh   = (__half*)(Mb + 256);
    __half* Kl   = Kh  + F16T;
    __half* Qh   = Kl  + F16T;
    __half* Ql   = Qh  + F16T;
    __half* Bh2  = Ql  + F16T;
    __half* Bl2  = Bh2 + F16T;
    __half* KTh  = Bl2 + F16T;
    __half* KTl  = KTh + F16T;
    __half* Sh   = KTl + F16T;
    __half* Sl   = Sh  + F16T;
    __half* WtTh = Sl  + F16T;
    __half* WtTl = WtTh + F16H;
    __half* WaTh = WtTl + F16H;
    __half* WaTl = WaTh + F16H;
    __half* UTh  = WaTl + F16H;
    __half* UTl  = UTh + F16H;
    __half* UwTh = UTl + F16H;
    __half* UwTl = UwTh + F16H;

    const int tid = threadIdx.x;
    const int lane = tid & 31, w = tid >> 5;
    const int g = lane >> 2, tg = lane & 3;
    const int arow = (lane & 7) + ((lane >> 3) & 1) * 8;
    const int acol = (lane >> 4) * 8;
    const int brow = ((lane >> 4) & 1) * 8 + (lane & 7);
    const int bcol = ((lane >> 3) & 1) * 8;

    const int pair = blockIdx.x >> 1;
    const int half = blockIdx.x & 1;
    const int col0 = half * 32;
    const int b = pair >> 4, h = pair & 15;

    for (int i = tid; i < 64 * HSX; i += 256) { Wt[i] = 0.f; Wa[i] = 0.f; }

    const size_t pbase = (size_t)pair * L_DIM * D_HEAD;
    const uint32_t khB = smem_u32(Kh), klB = smem_u32(Kl);

    for (int chunk = 0; chunk < N_CHUNK; chunk++) {
        __syncthreads();
        const size_t cb = pbase + (size_t)chunk * 64 * D_HEAD;
        for (int i2 = tid; i2 < 4096; i2 += 256) {
            int r = i2 >> 6, c = i2 & 63;
            float kv = g_kn[cb + i2];
            float qv = g_qn[cb + i2];
            float bv = g_bb[cb + i2];
            SPLIT_ST(Kh, Kl, r * HX + c, kv);
            SPLIT_ST(KTh, KTl, c * HX + r, kv);
            SPLIT_ST(Qh, Ql, r * HX + c, qv);
            SPLIT_ST(Bh2, Bl2, r * HX + c, bv);
        }
        for (int i2 = tid; i2 < 2048; i2 += 256) {
            int r = i2 >> 5, c = i2 & 31;
            Us[r * HSX + c] = g_vs[cb + r * 64 + col0 + c];
        }
        for (int i2 = tid; i2 < 2048; i2 += 256) {
            int m = i2 >> 5, n = i2 & 31;
            SPLIT_ST(WtTh, WtTl, n * HX + m, Wt[m * HSX + n]);
            SPLIT_ST(WaTh, WaTl, n * HX + m, Wa[m * HSX + n]);
        }
        __syncthreads();

        const float ts    = (float)(chunk * 64);
        const float tri0  = 0.5f * (1.f + ts) * ts;
        const float denw  = 0.5f * (65.f + ts) * (64.f + ts);
        const float Ssum  = 64.f * ts + 2080.f;
        const float coef1 = (ts / (ts + 64.f)) * ((1.f + ts) / (ts + 65.f));
        const float coef2 = (64.f / (ts + 64.f)) * ((2.f * ts + 65.f) / (ts + 65.f));

        /* PASS 1a: [B;Q] @ K^T -> T (warps 0-3, tril) / QK (warps 4-7) */
        {
            const uint32_t ahB = smem_u32((w < 4) ? Bh2 : Qh);
            const uint32_t alB = smem_u32((w < 4) ? Bl2 : Ql);
            const int r0 = (w & 3) * 16;
            float acc[8][4];
#pragma unroll
            for (int j = 0; j < 8; j++)
#pragma unroll
                for (int e = 0; e < 4; e++) acc[j][e] = 0.f;

#pragma unroll
            for (int ks = 0; ks < 4; ks++) {
                const int kc = ks * 16;
                uint32_t ah[4], al[4], bh[4][4], bl[4][4];
                const uint32_t aoff = ((r0 + arow) * HX + kc + acol) * 2;
                LDSM_X4(ah, ahB + aoff);
                LDSM_X4(al, alB + aoff);
#pragma unroll
                for (int nt = 0; nt < 4; nt++) {
                    const uint32_t boff = ((nt * 16 + brow) * HX + kc + bcol) * 2;
                    LDSM_X4(bh[nt], khB + boff);
                    LDSM_X4(bl[nt], klB + boff);
                }
#pragma unroll
                for (int j = 0; j < 8; j++) {
                    const int grp = j >> 1, p = (j & 1) * 2;
                    MMA_F16B(acc[j], ah, bh[grp][p], bh[grp][p + 1]);
                    MMA_F16B(acc[j], ah, bl[grp][p], bl[grp][p + 1]);
                    MMA_F16B(acc[j], al, bh[grp][p], bh[grp][p + 1]);
                }
            }
            if (w < 4) {
#pragma unroll
                for (int j = 0; j < 8; j++) {
                    const int C = j * 8 + tg * 2;
                    const int R1 = r0 + g, R2 = r0 + g + 8;
                    Ts[R1 * FS + C]     = (R1 > C)     ? acc[j][0] : 0.f;
                    Ts[R1 * FS + C + 1] = (R1 > C + 1) ? acc[j][1] : 0.f;
                    Ts[R2 * FS + C]     = (R2 > C)     ? acc[j][2] : 0.f;
                    Ts[R2 * FS + C + 1] = (R2 > C + 1) ? acc[j][3] : 0.f;
                }
            } else {
#pragma unroll
                for (int j = 0; j < 8; j++) {
                    const int C = j * 8 + tg * 2;
                    const int R1 = r0 + g, R2 = r0 + g + 8;
                    Qk[R1 * FS + C]     = acc[j][0];
                    Qk[R1 * FS + C + 1] = acc[j][1];
                    Qk[R2 * FS + C]     = acc[j][2];
                    Qk[R2 * FS + C + 1] = acc[j][3];
                }
            }
        }

        /* PASS 1b: RHS = V - B @ Wt */
        {
            const uint32_t b2h = smem_u32(Bh2), b2l = smem_u32(Bl2);
            const uint32_t wth = smem_u32(WtTh), wtl = smem_u32(WtTl);
            const int bm0 = (w & 3) * 16;
            const int bn0 = (w >> 2) * 16;
            float accB[2][4];
#pragma unroll
            for (int nt = 0; nt < 2; nt++)
#pragma unroll
                for (int e = 0; e < 4; e++) accB[nt][e] = 0.f;
#pragma unroll
            for (int ks = 0; ks < 4; ks++) {
                const int kc = ks * 16;
                uint32_t ah[4], al[4], bh[4], bl[4];
                const uint32_t aoff = ((bm0 + arow) * HX + kc + acol) * 2;
                LDSM_X4(ah, b2h + aoff);
                LDSM_X4(al, b2l + aoff);
                const uint32_t boff = ((bn0 + brow) * HX + kc + bcol) * 2;
                LDSM_X4(bh, wth + boff);
                LDSM_X4(bl, wtl + boff);
#pragma unroll
                for (int nt = 0; nt < 2; nt++) {
                    const int p = nt * 2;
                    MMA_F16B(accB[nt], ah, bh[p], bh[p + 1]);
                    MMA_F16B(accB[nt], ah, bl[p], bl[p + 1]);
                    MMA_F16B(accB[nt], al, bh[p], bh[p + 1]);
                }
            }
#pragma unroll
            for (int nt = 0; nt < 2; nt++) {
                const int col = bn0 + nt * 8 + tg * 2;
                const int R1 = bm0 + g, R2 = bm0 + g + 8;
                Us[R1 * HSX + col]     -= accB[nt][0];
                Us[R1 * HSX + col + 1] -= accB[nt][1];
                Us[R2 * HSX + col]     -= accB[nt][2];
                Us[R2 * HSX + col + 1] -= accB[nt][3];
            }
        }
        __syncthreads();

        /* C0: invert the 8 unit-lower 8x8 diagonal blocks */
        if (tid < 64) {
            const int blk = tid >> 3, c = tid & 7;
            const int r0 = blk * 8;
            float xcol[8];
#pragma unroll
            for (int r = 0; r < 8; r++) {
                float s = (r == c) ? 1.f : 0.f;
                for (int k2 = c; k2 < r; k2++)
                    s -= Ts[(r0 + r) * FS + r0 + k2] * xcol[k2];
                xcol[r] = s;
            }
#pragma unroll
            for (int r = 0; r < 8; r++) invD[(r0 + r) * 8 + c] = xcol[r];
        }
        __syncthreads();

        /* C: blocked forward substitution (I+T) U = RHS */
        {
            const int cc = tid & 31, rr = tid >> 5;
            for (int ib = 0; ib < 8; ib++) {
                const int r0 = ib * 8;
                float s = 0.f;
                for (int j = 0; j < r0; j++)
                    s += Ts[(r0 + rr) * FS + j] * Us[j * HSX + cc];
                float rhs = Us[(r0 + rr) * HSX + cc] - s;
                Mb[rr * 32 + cc] = rhs;
                __syncthreads();
                s = rhs;
                for (int k2 = 0; k2 < rr; k2++)
                    s += invD[(r0 + rr) * 8 + k2] * Mb[k2 * 32 + cc];
                Us[(r0 + rr) * HSX + cc] = s;
                __syncthreads();
            }
        }

        /* conversions: S = weights o QK; U^T and (U*w)^T in fp16 hi/lo */
        for (int i2 = tid; i2 < 4096; i2 += 256) {
            int r = i2 >> 6, c = i2 & 63;
            float rr2 = (float)r;
            float cs_r = (rr2 + 1.f) * ts + 0.5f * (rr2 + 1.f) * (rr2 + 2.f);
            float rdiv = 1.f / (tri0 + cs_r);
            float kf = (float)c;
            float csk_m = kf * ts + 0.5f * kf * (kf + 1.f);
            float num = cs_r - csk_m;
            float sfac = (num >= 0.f) ? num * rdiv : 0.f;
            float sv = sfac * Qk[r * FS + c];
            SPLIT_ST(Sh, Sl, r * HX + c, sv);
        }
        for (int i2 = tid; i2 < 2048; i2 += 256) {
            int c = i2 >> 6, r = i2 & 63;
            float u = Us[r * HSX + c];
            float rr2 = (float)r;
            float idxr = ts + rr2 + 1.f;
            float csrr = (rr2 + 1.f) * ts + 0.5f * (rr2 + 1.f) * (rr2 + 2.f);
            float wr = (idxr + Ssum - csrr) / denw;
            SPLIT_ST(UTh, UTl, c * HX + r, u);
            SPLIT_ST(UwTh, UwTl, c * HX + r, u * wr);
        }
        __syncthreads();

        /* PASS 2: warps 0-3 -> O (D + F); warps 4-7 -> H (W updates) */
        if (w < 4) {
            const int r0 = w * 16;
            const uint32_t qhB = smem_u32(Qh), qlB = smem_u32(Ql);
            const uint32_t shB = smem_u32(Sh), slB = smem_u32(Sl);
            const uint32_t wah = smem_u32(WaTh), wal = smem_u32(WaTl);
            const uint32_t wth = smem_u32(WtTh), wtl = smem_u32(WtTl);
            const uint32_t uth = smem_u32(UTh), utl = smem_u32(UTl);
            float aA[4][4], aT[4][4], aF[4][4];
#pragma unroll
            for (int nt = 0; nt < 4; nt++)
#pragma unroll
                for (int e = 0; e < 4; e++) { aA[nt][e] = 0.f; aT[nt][e] = 0.f; aF[nt][e] = 0.f; }

#pragma unroll
            for (int ks = 0; ks < 4; ks++) {
                const int kc = ks * 16;
                const uint32_t aoff = ((r0 + arow) * HX + kc + acol) * 2;
                uint32_t qh[4], ql[4], sh[4], sl[4];
                LDSM_X4(qh, qhB + aoff);
                LDSM_X4(ql, qlB + aoff);
                LDSM_X4(sh, shB + aoff);
                LDSM_X4(sl, slB + aoff);
                uint32_t bwa[2][4], bwa2[2][4], bwt[2][4], bwt2[2][4], bu[2][4], bu2[2][4];
#pragma unroll
                for (int a2 = 0; a2 < 2; a2++) {
                    const uint32_t boff = ((a2 * 16 + brow) * HX + kc + bcol) * 2;
                    LDSM_X4(bwa[a2], wah + boff);
                    LDSM_X4(bwa2[a2], wal + boff);
                    LDSM_X4(bwt[a2], wth + boff);
                    LDSM_X4(bwt2[a2], wtl + boff);
                    LDSM_X4(bu[a2], uth + boff);
                    LDSM_X4(bu2[a2], utl + boff);
                }
#pragma unroll
                for (int nt = 0; nt < 4; nt++) {
                    const int grp = nt >> 1, p = (nt & 1) * 2;
                    MMA_F16B(aA[nt], qh, bwa[grp][p], bwa[grp][p + 1]);
                    MMA_F16B(aA[nt], qh, bwa2[grp][p], bwa2[grp][p + 1]);
                    MMA_F16B(aA[nt], ql, bwa[grp][p], bwa[grp][p + 1]);
                    MMA_F16B(aT[nt], qh, bwt[grp][p], bwt[grp][p + 1]);
                    MMA_F16B(aT[nt], qh, bwt2[grp][p], bwt2[grp][p + 1]);
                    MMA_F16B(aT[nt], ql, bwt[grp][p], bwt[grp][p + 1]);
                    MMA_F16B(aF[nt], sh, bu[grp][p], bu[grp][p + 1]);
                    MMA_F16B(aF[nt], sh, bu2[grp][p], bu2[grp][p + 1]);
                    MMA_F16B(aF[nt], sl, bu[grp][p], bu[grp][p + 1]);
                }
            }
            const int r1 = r0 + g, r2 = r1 + 8;
            float f1 = (float)r1, f2 = (float)r2;
            float cs1 = (f1 + 1.f) * ts + 0.5f * (f1 + 1.f) * (f1 + 2.f);
            float cs2 = (f2 + 1.f) * ts + 0.5f * (f2 + 1.f) * (f2 + 2.f);
            float ar1 = tri0 / (tri0 + cs1);
            float ar2 = tri0 / (tri0 + cs2);
#pragma unroll
            for (int nt = 0; nt < 4; nt++) {
                const int cg = h * 64 + col0 + nt * 8 + tg * 2;
                int l1 = chunk * 64 + r1, l2 = chunk * 64 + r2;
                float2 v1 = make_float2(
                    ar1 * aA[nt][0] + (1.f - ar1) * aT[nt][0] + aF[nt][0],
                    ar1 * aA[nt][1] + (1.f - ar1) * aT[nt][1] + aF[nt][1]);
                float2 v2 = make_float2(
                    ar2 * aA[nt][2] + (1.f - ar2) * aT[nt][2] + aF[nt][2],
                    ar2 * aA[nt][3] + (1.f - ar2) * aT[nt][3] + aF[nt][3]);
                *(float2*)&g_o[((size_t)(b * L_DIM + l1)) * D_MODEL + cg] = v1;
                *(float2*)&g_o[((size_t)(b * L_DIM + l2)) * D_MODEL + cg] = v2;
            }
        } else {
            const int m0 = (w - 4) * 16;
            const uint32_t kth = smem_u32(KTh), ktl = smem_u32(KTl);
            const uint32_t uth = smem_u32(UTh), utl = smem_u32(UTl);
            const uint32_t uwh = smem_u32(UwTh), uwl = smem_u32(UwTl);
            float p1a[4][4], p2a[4][4];
#pragma unroll
            for (int nt = 0; nt < 4; nt++)
#pragma unroll
                for (int e = 0; e < 4; e++) { p1a[nt][e] = 0.f; p2a[nt][e] = 0.f; }

#pragma unroll
            for (int ks = 0; ks < 4; ks++) {
                const int kc = ks * 16;
                const uint32_t aoff = ((m0 + arow) * HX + kc + acol) * 2;
                uint32_t kh2[4], kl2[4];
                LDSM_X4(kh2, kth + aoff);
                LDSM_X4(kl2, ktl + aoff);
                uint32_t bu[2][4], bu2[2][4], bw[2][4], bw2[2][4];
#pragma unroll
                for (int a2 = 0; a2 < 2; a2++) {
                    const uint32_t boff = ((a2 * 16 + brow) * HX + kc + bcol) * 2;
                    LDSM_X4(bu[a2], uth + boff);
                    LDSM_X4(bu2[a2], utl + boff);
                    LDSM_X4(bw[a2], uwh + boff);
                    LDSM_X4(bw2[a2], uwl + boff);
                }
#pragma unroll
                for (int nt = 0; nt < 4; nt++) {
                    const int grp = nt >> 1, p = (nt & 1) * 2;
                    MMA_F16B(p1a[nt], kh2, bu[grp][p], bu[grp][p + 1]);
                    MMA_F16B(p1a[nt], kh2, bu2[grp][p], bu2[grp][p + 1]);
                    MMA_F16B(p1a[nt], kl2, bu[grp][p], bu[grp][p + 1]);
                    MMA_F16B(p2a[nt], kh2, bw[grp][p], bw[grp][p + 1]);
                    MMA_F16B(p2a[nt], kh2, bw2[grp][p], bw2[grp][p + 1]);
                    MMA_F16B(p2a[nt], kl2, bw[grp][p], bw[grp][p + 1]);
                }
            }
            const int m1 = m0 + g, m2 = m1 + 8;
#pragma unroll
            for (int nt = 0; nt < 4; nt++) {
                const int n = nt * 8 + tg * 2;
#pragma unroll
                for (int cc2 = 0; cc2 < 2; cc2++) {
                    int i1 = m1 * HSX + n + cc2;
                    float wo = Wt[i1];
                    Wa[i1] = coef1 * Wa[i1] + coef2 * wo + p2a[nt][cc2];
                    Wt[i1] = wo + p1a[nt][cc2];
                    int i2x = m2 * HSX + n + cc2;
                    wo = Wt[i2x];
                    Wa[i2x] = coef1 * Wa[i2x] + coef2 * wo + p2a[nt][2 + cc2];
                    Wt[i2x] = wo + p1a[nt][2 + cc2];
                }
            }
        }
    }
}

/* -------- RMS norm over head dim + fp16 (hi only) for final 2-pass GEMM ----- */
__global__ __launch_bounds__(256) void rms_split(const float* __restrict__ rms_w)
{
    const int bl = blockIdx.x, tid = threadIdx.x;
    float4 v = ((const float4*)g_o)[(size_t)bl * 256 + tid];
    float ss = v.x * v.x + v.y * v.y + v.z * v.z + v.w * v.w;
#pragma unroll
    for (int o = 8; o > 0; o >>= 1) ss += __shfl_xor_sync(0xffffffffu, ss, o);
    float scale = rsqrtf(ss * (1.f / 64.f) + 1e-6f);
    float4 rw = ((const float4*)rms_w)[tid & 15];
    float a0 = v.x * scale * rw.x, a1 = v.y * scale * rw.y;
    float a2 = v.z * scale * rw.z, a3 = v.w * scale * rw.w;
    __half2 h01 = __floats2half2_rn(a0, a1);
    __half2 h23 = __floats2half2_rn(a2, a3);
    ((uint2*)g_oh)[(size_t)bl * 256 + tid] = make_uint2(*(uint32_t*)&h01, *(uint32_t*)&h23);
}

/* ------------------------------- launcher ----------------------------------*/
extern "C" void kernel_launch(void* const* d_in, const int* in_sizes, int n_in,
                              void* d_out, int out_size)
{
    (void)in_sizes; (void)n_in; (void)out_size;
    const float* x     = (const float*)d_in[0];
    const float* Wk    = (const float*)d_in[1];
    const float* bk    = (const float*)d_in[2];
    const float* Wq    = (const float*)d_in[3];
    const float* bq    = (const float*)d_in[4];
    const float* Wv    = (const float*)d_in[5];
    const float* bv    = (const float*)d_in[6];
    const float* Wbeta = (const float*)d_in[7];
    const float* bbeta = (const float*)d_in[8];
    const float* ck    = (const float*)d_in[9];
    const float* cq    = (const float*)d_in[10];
    const float* cv    = (const float*)d_in[11];
    const float* rms_w = (const float*)d_in[12];
    const float* Wout  = (const float*)d_in[13];
    const float* bout  = (const float*)d_in[14];
    float* out = (float*)d_out;

    float *kpre, *qpre, *vpre;
    __half *xh, *oh, *wsh, *wsl;
    cudaGetSymbolAddress((void**)&kpre, g_kpre);
    cudaGetSymbolAddress((void**)&qpre, g_qpre);
    cudaGetSymbolAddress((void**)&vpre, g_vpre);
    cudaGetSymbolAddress((void**)&xh, g_xh);
    cudaGetSymbolAddress((void**)&oh, g_oh);
    cudaGetSymbolAddress((void**)&wsh, g_wsh);
    cudaGetSymbolAddress((void**)&wsl, g_wsl);

    split_hi<<<(ML * D_MODEL / 4 + 255) / 256, 256>>>(
        (const float4*)x, (uint2*)xh, ML * D_MODEL / 4);
    split_w4<<<(4 * DD / 4) / 256, 256>>>(
        (const float4*)Wk, (const float4*)Wq, (const float4*)Wv,
        (const float4*)Wout, (uint2*)wsh, (uint2*)wsl);

    cudaFuncSetAttribute(gemm_qkv1, cudaFuncAttributeMaxDynamicSharedMemorySize,
                         P1_BYTES);
    cudaFuncSetAttribute(gemm_h2b, cudaFuncAttributeMaxDynamicSharedMemorySize,
                         QSM_BYTES);

    gemm_qkv1<<<dim3(24, 64), 256, P1_BYTES>>>(
        xh, wsh, bk, bq, bv, kpre, qpre, vpre, ML, D_MODEL);

    prep4<<<B_DIM * (L_DIM / 4), 512>>>(x, Wbeta, bbeta, ck, cq, cv);

    cudaFuncSetAttribute(delta_kernel, cudaFuncAttributeMaxDynamicSharedMemorySize,
                         DSM_BYTES);
    delta_kernel<<<2 * N_PAIR, 256, DSM_BYTES>>>();

    rms_split<<<ML, 256>>>(rms_w);

    gemm_h2b<<<dim3(8, 64), 256, QSM_BYTES>>>(
        oh, wsh + 3 * DD, wsl, bout, out, ML, D_MODEL);
}